// round 3
// baseline (speedup 1.0000x reference)
#include <cuda_runtime.h>
#include <math.h>

// Problem constants
#define BSZ 8
#define CCH 256
#define NSP 1024           // H*W
#define NHH 4
#define DKD 64
#define CNT (CCH*NSP)      // 262144 elements per batch for GroupNorm

// -------- scratch (no allocations allowed) --------
__device__ float g_sums1[2*BSZ];                 // GN1: per-batch sum, sumsq
__device__ float g_sums2[2*BSZ];                 // GN2
__device__ float g_qkv [(size_t)BSZ*3*CCH*NSP];  // 24 MB
__device__ float g_attn[(size_t)BSZ*CCH*NSP];    // 8 MB
__device__ float g_x2  [(size_t)BSZ*CCH*NSP];    // 8 MB
__device__ float g_h1  [(size_t)BSZ*4*CCH*NSP];  // 32 MB

// -------- helpers --------
__device__ __forceinline__ void block_reduce2(float& s, float& s2) {
    #pragma unroll
    for (int o = 16; o; o >>= 1) {
        s  += __shfl_xor_sync(0xffffffffu, s,  o);
        s2 += __shfl_xor_sync(0xffffffffu, s2, o);
    }
    __shared__ float sh0[8], sh1[8];
    int w = threadIdx.x >> 5, l = threadIdx.x & 31;
    if (l == 0) { sh0[w] = s; sh1[w] = s2; }
    __syncthreads();
    if (w == 0) {
        s  = (l < 8) ? sh0[l] : 0.f;
        s2 = (l < 8) ? sh1[l] : 0.f;
        #pragma unroll
        for (int o = 4; o; o >>= 1) {
            s  += __shfl_xor_sync(0xffffffffu, s,  o);
            s2 += __shfl_xor_sync(0xffffffffu, s2, o);
        }
    }
}

__global__ void zero_stats_kernel() {
    int t = threadIdx.x;
    if (t < 2*BSZ) { g_sums1[t] = 0.f; g_sums2[t] = 0.f; }
}

// Per-batch sum / sumsq of x. grid (32 chunks, BSZ), 256 threads
__global__ void gn_stats_kernel(const float* __restrict__ x) {
    int b = blockIdx.y;
    const float* xb = x + (size_t)b * CNT;
    int base = blockIdx.x * (CNT / 32);
    float s = 0.f, s2 = 0.f;
    for (int i = threadIdx.x; i < CNT/32; i += 256) {
        float v = xb[base + i];
        s += v; s2 += v*v;
    }
    block_reduce2(s, s2);
    if (threadIdx.x == 0) {
        atomicAdd(&g_sums1[b*2],   s);
        atomicAdd(&g_sums1[b*2+1], s2);
    }
}

// ------------------------------------------------------------------
// Fused GEMM: C[b][m][n] = sum_k A[m][k] * Bin'[b][k][n]
//   NORMSRC: 0 = Bin used raw; 1 = GN with g_sums1; 2 = GN with g_sums2
//   BIAS: += bias[m]; SILU: x*sigmoid(x); RESID: out = resid + gamma*val
//   STATS: accumulate sum/sumsq of final output into g_sums2
// 64x64 tile, BK=16, 256 threads, 4x4 microtile. N fixed = 1024.
// ------------------------------------------------------------------
template<int NORMSRC, bool BIAS, bool SILU, bool RESID, bool STATS>
__global__ void gemm_fused_kernel(const float* __restrict__ A,
                                  const float* __restrict__ Bin,
                                  const float* __restrict__ gw,
                                  const float* __restrict__ gb,
                                  const float* __restrict__ bias,
                                  const float* __restrict__ resid,
                                  const float* __restrict__ gamma,
                                  float* __restrict__ Cout,
                                  int M, int K) {
    const int N = NSP;
    __shared__ float As[16][68];
    __shared__ float Bs[16][68];

    int b  = blockIdx.z;
    int m0 = blockIdx.y * 64, n0 = blockIdx.x * 64;
    int tid = threadIdx.x;
    int tx = tid & 15, ty = tid >> 4;

    float mean = 0.f, rstd = 0.f;
    if (NORMSRC) {
        const float* sums = (NORMSRC == 1) ? g_sums1 : g_sums2;
        float s = sums[b*2], s2 = sums[b*2+1];
        mean = s * (1.0f / CNT);
        float var = s2 * (1.0f / CNT) - mean * mean;
        rstd = rsqrtf(var + 1e-5f);
    }

    const float* Bb = Bin + (size_t)b * K * N;
    float acc[4][4] = {};

    int la_k = tid & 15, la_m = tid >> 4;   // A tile loader coords
    int lb_n = tid & 63, lb_k = tid >> 6;   // B tile loader coords

    for (int k0 = 0; k0 < K; k0 += 16) {
        #pragma unroll
        for (int r = 0; r < 4; r++)
            As[la_k][la_m + 16*r] = A[(size_t)(m0 + la_m + 16*r) * K + k0 + la_k];
        #pragma unroll
        for (int r = 0; r < 4; r++) {
            int k = k0 + lb_k + 4*r;
            float v = Bb[(size_t)k * N + n0 + lb_n];
            if (NORMSRC) v = (v - mean) * rstd * gw[k] + gb[k];
            Bs[lb_k + 4*r][lb_n] = v;
        }
        __syncthreads();
        #pragma unroll
        for (int kk = 0; kk < 16; kk++) {
            float a[4], bb[4];
            *(float4*)a  = *(const float4*)&As[kk][ty*4];
            *(float4*)bb = *(const float4*)&Bs[kk][tx*4];
            #pragma unroll
            for (int i = 0; i < 4; i++)
                #pragma unroll
                for (int j = 0; j < 4; j++)
                    acc[i][j] += a[i] * bb[j];
        }
        __syncthreads();
    }

    float g = RESID ? gamma[0] : 0.f;
    float s1 = 0.f, sq = 0.f;
    #pragma unroll
    for (int i = 0; i < 4; i++) {
        int m = m0 + ty*4 + i;
        float bi = BIAS ? bias[m] : 0.f;
        #pragma unroll
        for (int j = 0; j < 4; j++) {
            int n = n0 + tx*4 + j;
            float v = acc[i][j] + bi;
            if (SILU) v = v / (1.f + expf(-v));
            size_t idx = ((size_t)b * M + m) * N + n;
            if (RESID) v = resid[idx] + g * v;
            Cout[idx] = v;
            if (STATS) { s1 += v; sq += v*v; }
        }
    }
    if (STATS) {
        __syncthreads();
        block_reduce2(s1, sq);
        if (tid == 0) {
            atomicAdd(&g_sums2[b*2],   s1);
            atomicAdd(&g_sums2[b*2+1], sq);
        }
    }
}

// ------------------------------------------------------------------
// Flash attention: one block per (query-tile of 64, head, batch).
// 256 threads (16x16), online softmax, 64-wide K/V tiles.
// ------------------------------------------------------------------
__global__ void attn_kernel(const float* __restrict__ qkv, float* __restrict__ outp) {
    extern __shared__ float sm[];
    float* qs = sm;              // [64][68] q[d][i] (pre-scaled)
    float* ks = qs + 64*68;      // [64][68] k[d][j]  (also reused for output staging)
    float* ps = ks + 64*68;      // [64][68] p[i][j]
    float* vs = ps + 64*68;      // [64][65] v^T[j][d]

    int it = blockIdx.x, h = blockIdx.y, b = blockIdx.z;
    int tid = threadIdx.x, tx = tid & 15, ty = tid >> 4;
    int li = tid & 63, ld = tid >> 6;

    const float* qb = qkv + ((size_t)b*3*CCH +          h*DKD) * NSP + it*64;
    const float* kb = qkv + ((size_t)b*3*CCH +   CCH +  h*DKD) * NSP;
    const float* vb = qkv + ((size_t)b*3*CCH + 2*CCH +  h*DKD) * NSP;

    // load Q tile, pre-scale by 1/sqrt(dk). 256 thr x 16 iters = 64x64 tile.
    #pragma unroll
    for (int r = 0; r < 16; r++) {
        int d = ld + 4*r;
        qs[d*68 + li] = qb[(size_t)d * NSP + li] * 0.125f;
    }

    float m_r[4], l_r[4], acc[4][4];
    #pragma unroll
    for (int u = 0; u < 4; u++) {
        m_r[u] = -1e30f; l_r[u] = 0.f;
        #pragma unroll
        for (int v = 0; v < 4; v++) acc[u][v] = 0.f;
    }

    for (int kt = 0; kt < 16; kt++) {
        __syncthreads();
        #pragma unroll
        for (int r = 0; r < 16; r++) {
            int d = ld + 4*r;
            ks[d*68 + li]  = kb[(size_t)d * NSP + kt*64 + li];
            vs[li*65 + d]  = vb[(size_t)d * NSP + kt*64 + li];
        }
        __syncthreads();

        // scores s[i][j] = sum_d qs[d][i]*ks[d][j]
        float s[4][4] = {};
        #pragma unroll 8
        for (int d = 0; d < 64; d++) {
            float q4[4], k4[4];
            *(float4*)q4 = *(const float4*)&qs[d*68 + ty*4];
            *(float4*)k4 = *(const float4*)&ks[d*68 + tx*4];
            #pragma unroll
            for (int u = 0; u < 4; u++)
                #pragma unroll
                for (int v = 0; v < 4; v++)
                    s[u][v] += q4[u] * k4[v];
        }

        // online softmax per row
        #pragma unroll
        for (int u = 0; u < 4; u++) {
            float mloc = fmaxf(fmaxf(s[u][0], s[u][1]), fmaxf(s[u][2], s[u][3]));
            #pragma unroll
            for (int o = 1; o < 16; o <<= 1)
                mloc = fmaxf(mloc, __shfl_xor_sync(0xffffffffu, mloc, o));
            float mnew  = fmaxf(m_r[u], mloc);
            float alpha = expf(m_r[u] - mnew);
            m_r[u] = mnew;
            float ls = 0.f;
            #pragma unroll
            for (int v = 0; v < 4; v++) {
                s[u][v] = expf(s[u][v] - mnew);
                ls += s[u][v];
            }
            #pragma unroll
            for (int o = 1; o < 16; o <<= 1)
                ls += __shfl_xor_sync(0xffffffffu, ls, o);
            l_r[u] = l_r[u] * alpha + ls;
            #pragma unroll
            for (int v = 0; v < 4; v++) {
                acc[u][v] *= alpha;
                ps[(ty*4 + u)*68 + tx*4 + v] = s[u][v];
            }
        }
        __syncthreads();

        // out[i][d] += sum_j p[i][j] * v[d][j]
        #pragma unroll 8
        for (int j = 0; j < 64; j++) {
            float pv[4], vv[4];
            #pragma unroll
            for (int u = 0; u < 4; u++) pv[u] = ps[(ty*4 + u)*68 + j];
            #pragma unroll
            for (int v = 0; v < 4; v++) vv[v] = vs[j*65 + tx*4 + v];
            #pragma unroll
            for (int u = 0; u < 4; u++)
                #pragma unroll
                for (int v = 0; v < 4; v++)
                    acc[u][v] += pv[u] * vv[v];
        }
    }

    // finalize and stage through smem (ks reused) for coalesced writes
    __syncthreads();
    #pragma unroll
    for (int u = 0; u < 4; u++) {
        float inv = 1.0f / l_r[u];
        #pragma unroll
        for (int v = 0; v < 4; v++)
            ks[(tx*4 + v)*68 + ty*4 + u] = acc[u][v] * inv;   // os[d][i]
    }
    __syncthreads();
    float* ob = outp + ((size_t)b*CCH + h*DKD) * NSP + it*64;
    #pragma unroll
    for (int r = 0; r < 16; r++) {
        int d = ld + 4*r;
        ob[(size_t)d * NSP + li] = ks[d*68 + li];
    }
}

// ------------------------------------------------------------------
extern "C" void kernel_launch(void* const* d_in, const int* in_sizes, int n_in,
                              void* d_out, int out_size) {
    const float* x     = (const float*)d_in[0];
    const float* qkv_w = (const float*)d_in[1];
    const float* uh_w  = (const float*)d_in[2];
    const float* uh_b  = (const float*)d_in[3];
    const float* n1_w  = (const float*)d_in[4];
    const float* n1_b  = (const float*)d_in[5];
    const float* n2_w  = (const float*)d_in[6];
    const float* n2_b  = (const float*)d_in[7];
    const float* f1_w  = (const float*)d_in[8];
    const float* f1_b  = (const float*)d_in[9];
    const float* f2_w  = (const float*)d_in[10];
    const float* f2_b  = (const float*)d_in[11];
    const float* g_at  = (const float*)d_in[12];
    const float* g_ff  = (const float*)d_in[13];
    float* out = (float*)d_out;

    float *qkv_buf, *attn_buf, *x2_buf, *h1_buf;
    cudaGetSymbolAddress((void**)&qkv_buf,  g_qkv);
    cudaGetSymbolAddress((void**)&attn_buf, g_attn);
    cudaGetSymbolAddress((void**)&x2_buf,   g_x2);
    cudaGetSymbolAddress((void**)&h1_buf,   g_h1);

    cudaFuncSetAttribute(attn_kernel,
                         cudaFuncAttributeMaxDynamicSharedMemorySize, 70000);

    // 1) zero stats accumulators
    zero_stats_kernel<<<1, 32>>>();

    // 2) GN1 stats on x
    gn_stats_kernel<<<dim3(32, BSZ), 256>>>(x);

    // 3) qkv = qkv_w @ GN1(x)       [M=768, K=256]
    gemm_fused_kernel<1, false, false, false, false>
        <<<dim3(16, 12, BSZ), 256>>>(qkv_w, x, n1_w, n1_b,
                                     nullptr, nullptr, nullptr, qkv_buf, 3*CCH, CCH);

    // 4) attention
    attn_kernel<<<dim3(16, NHH, BSZ), 256, 70000>>>(qkv_buf, attn_buf);

    // 5) x2 = x + g_attn * (uh_w @ attn + uh_b); also accumulate GN2 stats
    gemm_fused_kernel<0, true, false, true, true>
        <<<dim3(16, 4, BSZ), 256>>>(uh_w, attn_buf, nullptr, nullptr,
                                    uh_b, x, g_at, x2_buf, CCH, CCH);

    // 6) h1 = silu(f1_w @ GN2(x2) + f1_b)   [M=1024, K=256]
    gemm_fused_kernel<2, true, true, false, false>
        <<<dim3(16, 16, BSZ), 256>>>(f1_w, x2_buf, n2_w, n2_b,
                                     f1_b, nullptr, nullptr, h1_buf, 4*CCH, CCH);

    // 7) out = x2 + g_ffn * (f2_w @ h1 + f2_b)   [M=256, K=1024]
    gemm_fused_kernel<0, true, false, true, false>
        <<<dim3(16, 4, BSZ), 256>>>(f2_w, h1_buf, nullptr, nullptr,
                                    f2_b, x2_buf, g_ff, out, CCH, 4*CCH);
}

// round 5
// speedup vs baseline: 1.1993x; 1.1993x over previous
#include <cuda_runtime.h>
#include <cuda_bf16.h>
#include <math.h>
#include <stdint.h>

#define BSZ 8
#define CCH 256
#define NSP 1024
#define NHH 4
#define DKD 64
#define CNT (CCH*NSP)

__device__ float g_sums1[2*BSZ];
__device__ float g_sums2[2*BSZ];
__device__ float g_qkv [(size_t)BSZ*3*CCH*NSP];
__device__ float g_attn[(size_t)BSZ*CCH*NSP];
__device__ float g_x2  [(size_t)BSZ*CCH*NSP];
__device__ float g_h1  [(size_t)BSZ*4*CCH*NSP];

// ---------- reductions / stats ----------
__device__ __forceinline__ void block_reduce2(float& s, float& s2) {
    #pragma unroll
    for (int o = 16; o; o >>= 1) {
        s  += __shfl_xor_sync(0xffffffffu, s,  o);
        s2 += __shfl_xor_sync(0xffffffffu, s2, o);
    }
    __shared__ float sh0[8], sh1[8];
    int w = threadIdx.x >> 5, l = threadIdx.x & 31;
    if (l == 0) { sh0[w] = s; sh1[w] = s2; }
    __syncthreads();
    if (w == 0) {
        s  = (l < 8) ? sh0[l] : 0.f;
        s2 = (l < 8) ? sh1[l] : 0.f;
        #pragma unroll
        for (int o = 4; o; o >>= 1) {
            s  += __shfl_xor_sync(0xffffffffu, s,  o);
            s2 += __shfl_xor_sync(0xffffffffu, s2, o);
        }
    }
}

__global__ void zero_stats_kernel() {
    int t = threadIdx.x;
    if (t < 2*BSZ) { g_sums1[t] = 0.f; g_sums2[t] = 0.f; }
}

__global__ void gn_stats_kernel(const float* __restrict__ x) {
    int b = blockIdx.y;
    const float* xb = x + (size_t)b * CNT;
    int base = blockIdx.x * (CNT / 32);
    float s = 0.f, s2 = 0.f;
    for (int i = threadIdx.x; i < CNT/32; i += 256) {
        float v = xb[base + i];
        s += v; s2 += v*v;
    }
    block_reduce2(s, s2);
    if (threadIdx.x == 0) {
        atomicAdd(&g_sums1[b*2],   s);
        atomicAdd(&g_sums1[b*2+1], s2);
    }
}

// ---------- HMMA helpers (baseline PTX, works on plain sm_100 target) ----------
#define MMA_B16(c, a, b0, b1) \
  asm volatile("mma.sync.aligned.m16n8k16.row.col.f32.bf16.bf16.f32 " \
    "{%0,%1,%2,%3}, {%4,%5,%6,%7}, {%8,%9}, {%0,%1,%2,%3};" \
    : "+f"((c)[0]),"+f"((c)[1]),"+f"((c)[2]),"+f"((c)[3]) \
    : "r"((a)[0]),"r"((a)[1]),"r"((a)[2]),"r"((a)[3]), "r"(b0),"r"(b1))

__device__ __forceinline__ void split_bf16(float v, __nv_bfloat16& h, __nv_bfloat16& l) {
    h = __float2bfloat16(v);
    l = __float2bfloat16(v - __bfloat162float(h));
}

// ---------- fused HMMA GEMM ----------
// D[ch 128, tok 128] = W[m0..m0+128, K] @ Act'[K, tok]; Act channel-major [b][K][NSP]
// NORMSRC: 0 raw, 1 GN(g_sums1), 2 GN(g_sums2) applied to Act rows
// EPI: 0 plain(qkv) 1 bias+resid*g+stats(x2) 2 bias+silu(h1) 3 bias+resid*g(final)
#define LDT 34   // smem row stride in bf16 (32 k + pad 2)

template<int K, int NORMSRC, int EPI>
__global__ void __launch_bounds__(256) gemm_mma(
    const float* __restrict__ Act, const float* __restrict__ W,
    const float* __restrict__ gw, const float* __restrict__ gb,
    const float* __restrict__ bias, const float* __restrict__ resid,
    const float* __restrict__ gamma, float* __restrict__ out)
{
    constexpr int MT = (EPI==0)?768:(EPI==2)?1024:256;
    __shared__ __nv_bfloat16 AsH[128*LDT], AsL[128*LDT];   // weights  [m][k]
    __shared__ __nv_bfloat16 BsH[128*LDT], BsL[128*LDT];   // acts     [tok][k]

    int tid = threadIdx.x, lane = tid & 31, w = tid >> 5;
    int wm = w & 3, wn = w >> 2;              // 4 (M) x 2 (N) warps
    int t0 = blockIdx.x * 128, m0 = blockIdx.y * 128, b = blockIdx.z;

    float mean = 0.f, rstd = 0.f;
    if (NORMSRC) {
        const float* s = (NORMSRC == 1) ? g_sums1 : g_sums2;
        mean = s[b*2] * (1.f/CNT);
        rstd = rsqrtf(s[b*2+1] * (1.f/CNT) - mean*mean + 1e-5f);
    }

    float acc[2][8][4] = {};

    const int g = lane >> 2, tq = lane & 3;   // fragment coords

    for (int c = 0; c < K/32; c++) {
        int kc = c * 32;
        // ---- stage activations (transpose k-major -> token-major, GN fused) ----
        {
            int kk = tid >> 3, tg = (tid & 7) * 16, ch = kc + kk;
            float gwc = NORMSRC ? gw[ch] : 1.f, gbc = NORMSRC ? gb[ch] : 0.f;
            const float* p = Act + ((size_t)b*K + ch)*NSP + t0 + tg;
            #pragma unroll
            for (int j = 0; j < 4; j++) {
                float4 f = *(const float4*)(p + j*4);
                float v4[4] = {f.x, f.y, f.z, f.w};
                #pragma unroll
                for (int e = 0; e < 4; e++) {
                    float v = NORMSRC ? (v4[e]-mean)*rstd*gwc + gbc : v4[e];
                    __nv_bfloat16 h, l; split_bf16(v, h, l);
                    int tok = tg + j*4 + e;
                    BsH[tok*LDT + kk] = h;
                    BsL[tok*LDT + kk] = l;
                }
            }
        }
        // ---- stage weights (contiguous k) ----
        {
            int m = tid >> 1, kh = (tid & 1) * 16;
            const float* p = W + (size_t)(m0 + m)*K + kc + kh;
            #pragma unroll
            for (int j = 0; j < 4; j++) {
                float4 f = *(const float4*)(p + j*4);
                float v4[4] = {f.x, f.y, f.z, f.w};
                #pragma unroll
                for (int e = 0; e < 4; e++) {
                    __nv_bfloat16 h, l; split_bf16(v4[e], h, l);
                    AsH[m*LDT + kh + j*4 + e] = h;
                    AsL[m*LDT + kh + j*4 + e] = l;
                }
            }
        }
        __syncthreads();

        #pragma unroll
        for (int ks = 0; ks < 2; ks++) {
            int kb = ks * 16;
            uint32_t aH[2][4], aL[2][4];
            #pragma unroll
            for (int mf = 0; mf < 2; mf++) {
                int r0 = wm*32 + mf*16 + g;
                int kcol = kb + tq*2;
                aH[mf][0] = *(const uint32_t*)&AsH[ r0    *LDT + kcol    ];
                aH[mf][1] = *(const uint32_t*)&AsH[(r0+8) *LDT + kcol    ];
                aH[mf][2] = *(const uint32_t*)&AsH[ r0    *LDT + kcol + 8];
                aH[mf][3] = *(const uint32_t*)&AsH[(r0+8) *LDT + kcol + 8];
                aL[mf][0] = *(const uint32_t*)&AsL[ r0    *LDT + kcol    ];
                aL[mf][1] = *(const uint32_t*)&AsL[(r0+8) *LDT + kcol    ];
                aL[mf][2] = *(const uint32_t*)&AsL[ r0    *LDT + kcol + 8];
                aL[mf][3] = *(const uint32_t*)&AsL[(r0+8) *LDT + kcol + 8];
            }
            #pragma unroll
            for (int nf = 0; nf < 8; nf++) {
                int n = wn*64 + nf*8 + g;
                int kr = kb + tq*2;
                uint32_t bH0 = *(const uint32_t*)&BsH[n*LDT + kr    ];
                uint32_t bH1 = *(const uint32_t*)&BsH[n*LDT + kr + 8];
                uint32_t bL0 = *(const uint32_t*)&BsL[n*LDT + kr    ];
                uint32_t bL1 = *(const uint32_t*)&BsL[n*LDT + kr + 8];
                #pragma unroll
                for (int mf = 0; mf < 2; mf++) {
                    MMA_B16(acc[mf][nf], aH[mf], bH0, bH1);
                    MMA_B16(acc[mf][nf], aH[mf], bL0, bL1);
                    MMA_B16(acc[mf][nf], aL[mf], bH0, bH1);
                }
            }
        }
        __syncthreads();
    }

    // ---- epilogue ----
    float gm = (EPI==1 || EPI==3) ? gamma[0] : 0.f;
    float s1 = 0.f, sq = 0.f;
    #pragma unroll
    for (int mf = 0; mf < 2; mf++) {
        int row = m0 + wm*32 + mf*16 + g;
        float bi0 = (EPI!=0) ? bias[row]     : 0.f;
        float bi8 = (EPI!=0) ? bias[row + 8] : 0.f;
        #pragma unroll
        for (int nf = 0; nf < 8; nf++) {
            int col = t0 + wn*64 + nf*8 + tq*2;
            float v00 = acc[mf][nf][0] + bi0;
            float v01 = acc[mf][nf][1] + bi0;
            float v10 = acc[mf][nf][2] + bi8;
            float v11 = acc[mf][nf][3] + bi8;
            size_t i0 = ((size_t)b*MT + row    )*NSP + col;
            size_t i8 = ((size_t)b*MT + row + 8)*NSP + col;
            if (EPI == 2) {
                v00 = v00 / (1.f + __expf(-v00));
                v01 = v01 / (1.f + __expf(-v01));
                v10 = v10 / (1.f + __expf(-v10));
                v11 = v11 / (1.f + __expf(-v11));
            } else if (EPI == 1 || EPI == 3) {
                float2 r0 = *(const float2*)(resid + i0);
                float2 r8 = *(const float2*)(resid + i8);
                v00 = r0.x + gm*v00;  v01 = r0.y + gm*v01;
                v10 = r8.x + gm*v10;  v11 = r8.y + gm*v11;
                if (EPI == 1) {
                    s1 += v00+v01+v10+v11;
                    sq += v00*v00 + v01*v01 + v10*v10 + v11*v11;
                }
            }
            *(float2*)(out + i0) = make_float2(v00, v01);
            *(float2*)(out + i8) = make_float2(v10, v11);
        }
    }
    if (EPI == 1) {
        block_reduce2(s1, sq);
        if (tid == 0) { atomicAdd(&g_sums2[b*2], s1); atomicAdd(&g_sums2[b*2+1], sq); }
    }
}

// ---------- flash attention (unchanged, known-passing) ----------
__global__ void attn_kernel(const float* __restrict__ qkv, float* __restrict__ outp) {
    extern __shared__ float sm[];
    float* qs = sm;
    float* ks = qs + 64*68;
    float* ps = ks + 64*68;
    float* vs = ps + 64*68;

    int it = blockIdx.x, h = blockIdx.y, b = blockIdx.z;
    int tid = threadIdx.x, tx = tid & 15, ty = tid >> 4;
    int li = tid & 63, ld = tid >> 6;

    const float* qb = qkv + ((size_t)b*3*CCH +          h*DKD) * NSP + it*64;
    const float* kb = qkv + ((size_t)b*3*CCH +   CCH +  h*DKD) * NSP;
    const float* vb = qkv + ((size_t)b*3*CCH + 2*CCH +  h*DKD) * NSP;

    #pragma unroll
    for (int r = 0; r < 16; r++) {
        int d = ld + 4*r;
        qs[d*68 + li] = qb[(size_t)d * NSP + li] * 0.125f;
    }

    float m_r[4], l_r[4], acc[4][4];
    #pragma unroll
    for (int u = 0; u < 4; u++) {
        m_r[u] = -1e30f; l_r[u] = 0.f;
        #pragma unroll
        for (int v = 0; v < 4; v++) acc[u][v] = 0.f;
    }

    for (int kt = 0; kt < 16; kt++) {
        __syncthreads();
        #pragma unroll
        for (int r = 0; r < 16; r++) {
            int d = ld + 4*r;
            ks[d*68 + li]  = kb[(size_t)d * NSP + kt*64 + li];
            vs[li*65 + d]  = vb[(size_t)d * NSP + kt*64 + li];
        }
        __syncthreads();

        float s[4][4] = {};
        #pragma unroll 8
        for (int d = 0; d < 64; d++) {
            float q4[4], k4[4];
            *(float4*)q4 = *(const float4*)&qs[d*68 + ty*4];
            *(float4*)k4 = *(const float4*)&ks[d*68 + tx*4];
            #pragma unroll
            for (int u = 0; u < 4; u++)
                #pragma unroll
                for (int v = 0; v < 4; v++)
                    s[u][v] += q4[u] * k4[v];
        }

        #pragma unroll
        for (int u = 0; u < 4; u++) {
            float mloc = fmaxf(fmaxf(s[u][0], s[u][1]), fmaxf(s[u][2], s[u][3]));
            #pragma unroll
            for (int o = 1; o < 16; o <<= 1)
                mloc = fmaxf(mloc, __shfl_xor_sync(0xffffffffu, mloc, o));
            float mnew  = fmaxf(m_r[u], mloc);
            float alpha = expf(m_r[u] - mnew);
            m_r[u] = mnew;
            float ls = 0.f;
            #pragma unroll
            for (int v = 0; v < 4; v++) {
                s[u][v] = expf(s[u][v] - mnew);
                ls += s[u][v];
            }
            #pragma unroll
            for (int o = 1; o < 16; o <<= 1)
                ls += __shfl_xor_sync(0xffffffffu, ls, o);
            l_r[u] = l_r[u] * alpha + ls;
            #pragma unroll
            for (int v = 0; v < 4; v++) {
                acc[u][v] *= alpha;
                ps[(ty*4 + u)*68 + tx*4 + v] = s[u][v];
            }
        }
        __syncthreads();

        #pragma unroll 8
        for (int j = 0; j < 64; j++) {
            float pv[4], vv[4];
            #pragma unroll
            for (int u = 0; u < 4; u++) pv[u] = ps[(ty*4 + u)*68 + j];
            #pragma unroll
            for (int v = 0; v < 4; v++) vv[v] = vs[j*65 + tx*4 + v];
            #pragma unroll
            for (int u = 0; u < 4; u++)
                #pragma unroll
                for (int v = 0; v < 4; v++)
                    acc[u][v] += pv[u] * vv[v];
        }
    }

    __syncthreads();
    #pragma unroll
    for (int u = 0; u < 4; u++) {
        float inv = 1.0f / l_r[u];
        #pragma unroll
        for (int v = 0; v < 4; v++)
            ks[(tx*4 + v)*68 + ty*4 + u] = acc[u][v] * inv;
    }
    __syncthreads();
    float* ob = outp + ((size_t)b*CCH + h*DKD) * NSP + it*64;
    #pragma unroll
    for (int r = 0; r < 16; r++) {
        int d = ld + 4*r;
        ob[(size_t)d * NSP + li] = ks[d*68 + li];
    }
}

// ---------- launch ----------
extern "C" void kernel_launch(void* const* d_in, const int* in_sizes, int n_in,
                              void* d_out, int out_size) {
    const float* x     = (const float*)d_in[0];
    const float* qkv_w = (const float*)d_in[1];
    const float* uh_w  = (const float*)d_in[2];
    const float* uh_b  = (const float*)d_in[3];
    const float* n1_w  = (const float*)d_in[4];
    const float* n1_b  = (const float*)d_in[5];
    const float* n2_w  = (const float*)d_in[6];
    const float* n2_b  = (const float*)d_in[7];
    const float* f1_w  = (const float*)d_in[8];
    const float* f1_b  = (const float*)d_in[9];
    const float* f2_w  = (const float*)d_in[10];
    const float* f2_b  = (const float*)d_in[11];
    const float* g_at  = (const float*)d_in[12];
    const float* g_ff  = (const float*)d_in[13];
    float* out = (float*)d_out;

    float *qkv_buf, *attn_buf, *x2_buf, *h1_buf;
    cudaGetSymbolAddress((void**)&qkv_buf,  g_qkv);
    cudaGetSymbolAddress((void**)&attn_buf, g_attn);
    cudaGetSymbolAddress((void**)&x2_buf,   g_x2);
    cudaGetSymbolAddress((void**)&h1_buf,   g_h1);

    cudaFuncSetAttribute(attn_kernel, cudaFuncAttributeMaxDynamicSharedMemorySize, 70000);

    zero_stats_kernel<<<1, 32>>>();
    gn_stats_kernel<<<dim3(32, BSZ), 256>>>(x);

    // qkv = qkv_w @ GN1(x)
    gemm_mma<256,1,0><<<dim3(8,6,BSZ), 256>>>(
        x, qkv_w, n1_w, n1_b, nullptr, nullptr, nullptr, qkv_buf);

    attn_kernel<<<dim3(16, NHH, BSZ), 256, 70000>>>(qkv_buf, attn_buf);

    // x2 = x + g_at*(uh_w@attn + uh_b), + GN2 stats
    gemm_mma<256,0,1><<<dim3(8,2,BSZ), 256>>>(
        attn_buf, uh_w, nullptr, nullptr, uh_b, x, g_at, x2_buf);

    // h1 = silu(f1_w @ GN2(x2) + f1_b)
    gemm_mma<256,2,2><<<dim3(8,8,BSZ), 256>>>(
        x2_buf, f1_w, n2_w, n2_b, f1_b, nullptr, nullptr, h1_buf);

    // out = x2 + g_ff*(f2_w@h1 + f2_b)
    gemm_mma<1024,0,3><<<dim3(8,2,BSZ), 256>>>(
        h1_buf, f2_w, nullptr, nullptr, f2_b, x2_buf, g_ff, out);
}

// round 6
// speedup vs baseline: 1.2700x; 1.0589x over previous
#include <cuda_runtime.h>
#include <cuda_bf16.h>
#include <math.h>
#include <stdint.h>

#define BSZ 8
#define CCH 256
#define NSP 1024
#define NHH 4
#define DKD 64
#define CNT (CCH*NSP)

__device__ float g_sums1[2*BSZ];
__device__ float g_sums2[2*BSZ];
__device__ float g_qkv [(size_t)BSZ*3*CCH*NSP];
__device__ float g_attn[(size_t)BSZ*CCH*NSP];
__device__ float g_x2  [(size_t)BSZ*CCH*NSP];
__device__ float g_h1  [(size_t)BSZ*4*CCH*NSP];

// ---------- reductions / stats ----------
__device__ __forceinline__ void block_reduce2(float& s, float& s2) {
    #pragma unroll
    for (int o = 16; o; o >>= 1) {
        s  += __shfl_xor_sync(0xffffffffu, s,  o);
        s2 += __shfl_xor_sync(0xffffffffu, s2, o);
    }
    __shared__ float sh0[8], sh1[8];
    int w = threadIdx.x >> 5, l = threadIdx.x & 31;
    if (l == 0) { sh0[w] = s; sh1[w] = s2; }
    __syncthreads();
    if (w == 0) {
        s  = (l < 8) ? sh0[l] : 0.f;
        s2 = (l < 8) ? sh1[l] : 0.f;
        #pragma unroll
        for (int o = 4; o; o >>= 1) {
            s  += __shfl_xor_sync(0xffffffffu, s,  o);
            s2 += __shfl_xor_sync(0xffffffffu, s2, o);
        }
    }
}

__global__ void zero_stats_kernel() {
    int t = threadIdx.x;
    if (t < 2*BSZ) { g_sums1[t] = 0.f; g_sums2[t] = 0.f; }
}

__global__ void gn_stats_kernel(const float* __restrict__ x) {
    int b = blockIdx.y;
    const float* xb = x + (size_t)b * CNT;
    int base = blockIdx.x * (CNT / 32);
    float s = 0.f, s2 = 0.f;
    for (int i = threadIdx.x; i < CNT/32; i += 256) {
        float v = xb[base + i];
        s += v; s2 += v*v;
    }
    block_reduce2(s, s2);
    if (threadIdx.x == 0) {
        atomicAdd(&g_sums1[b*2],   s);
        atomicAdd(&g_sums1[b*2+1], s2);
    }
}

// ---------- HMMA helpers ----------
#define MMA_B16(c, a, b0, b1) \
  asm volatile("mma.sync.aligned.m16n8k16.row.col.f32.bf16.bf16.f32 " \
    "{%0,%1,%2,%3}, {%4,%5,%6,%7}, {%8,%9}, {%0,%1,%2,%3};" \
    : "+f"((c)[0]),"+f"((c)[1]),"+f"((c)[2]),"+f"((c)[3]) \
    : "r"((a)[0]),"r"((a)[1]),"r"((a)[2]),"r"((a)[3]), "r"(b0),"r"(b1))

__device__ __forceinline__ void split_bf16(float v, __nv_bfloat16& h, __nv_bfloat16& l) {
    h = __float2bfloat16(v);
    l = __float2bfloat16(v - __bfloat162float(h));
}
__device__ __forceinline__ void pack2(float a, float b, uint32_t& h, uint32_t& l) {
    __nv_bfloat162 hb = __floats2bfloat162_rn(a, b);
    float ra = a - __bfloat162float(hb.x);
    float rb = b - __bfloat162float(hb.y);
    __nv_bfloat162 lb = __floats2bfloat162_rn(ra, rb);
    h = *(uint32_t*)&hb; l = *(uint32_t*)&lb;
}

// ---------- fused HMMA GEMM (unchanged from passing R5) ----------
#define LDT 34

template<int K, int NORMSRC, int EPI>
__global__ void __launch_bounds__(256) gemm_mma(
    const float* __restrict__ Act, const float* __restrict__ W,
    const float* __restrict__ gw, const float* __restrict__ gb,
    const float* __restrict__ bias, const float* __restrict__ resid,
    const float* __restrict__ gamma, float* __restrict__ out)
{
    constexpr int MT = (EPI==0)?768:(EPI==2)?1024:256;
    __shared__ __nv_bfloat16 AsH[128*LDT], AsL[128*LDT];
    __shared__ __nv_bfloat16 BsH[128*LDT], BsL[128*LDT];

    int tid = threadIdx.x, lane = tid & 31, w = tid >> 5;
    int wm = w & 3, wn = w >> 2;
    int t0 = blockIdx.x * 128, m0 = blockIdx.y * 128, b = blockIdx.z;

    float mean = 0.f, rstd = 0.f;
    if (NORMSRC) {
        const float* s = (NORMSRC == 1) ? g_sums1 : g_sums2;
        mean = s[b*2] * (1.f/CNT);
        rstd = rsqrtf(s[b*2+1] * (1.f/CNT) - mean*mean + 1e-5f);
    }

    float acc[2][8][4] = {};
    const int g = lane >> 2, tq = lane & 3;

    for (int c = 0; c < K/32; c++) {
        int kc = c * 32;
        {
            int kk = tid >> 3, tg = (tid & 7) * 16, ch = kc + kk;
            float gwc = NORMSRC ? gw[ch] : 1.f, gbc = NORMSRC ? gb[ch] : 0.f;
            const float* p = Act + ((size_t)b*K + ch)*NSP + t0 + tg;
            #pragma unroll
            for (int j = 0; j < 4; j++) {
                float4 f = *(const float4*)(p + j*4);
                float v4[4] = {f.x, f.y, f.z, f.w};
                #pragma unroll
                for (int e = 0; e < 4; e++) {
                    float v = NORMSRC ? (v4[e]-mean)*rstd*gwc + gbc : v4[e];
                    __nv_bfloat16 h, l; split_bf16(v, h, l);
                    int tok = tg + j*4 + e;
                    BsH[tok*LDT + kk] = h;
                    BsL[tok*LDT + kk] = l;
                }
            }
        }
        {
            int m = tid >> 1, kh = (tid & 1) * 16;
            const float* p = W + (size_t)(m0 + m)*K + kc + kh;
            #pragma unroll
            for (int j = 0; j < 4; j++) {
                float4 f = *(const float4*)(p + j*4);
                float v4[4] = {f.x, f.y, f.z, f.w};
                #pragma unroll
                for (int e = 0; e < 4; e++) {
                    __nv_bfloat16 h, l; split_bf16(v4[e], h, l);
                    AsH[m*LDT + kh + j*4 + e] = h;
                    AsL[m*LDT + kh + j*4 + e] = l;
                }
            }
        }
        __syncthreads();

        #pragma unroll
        for (int ks = 0; ks < 2; ks++) {
            int kb = ks * 16;
            uint32_t aH[2][4], aL[2][4];
            #pragma unroll
            for (int mf = 0; mf < 2; mf++) {
                int r0 = wm*32 + mf*16 + g;
                int kcol = kb + tq*2;
                aH[mf][0] = *(const uint32_t*)&AsH[ r0    *LDT + kcol    ];
                aH[mf][1] = *(const uint32_t*)&AsH[(r0+8) *LDT + kcol    ];
                aH[mf][2] = *(const uint32_t*)&AsH[ r0    *LDT + kcol + 8];
                aH[mf][3] = *(const uint32_t*)&AsH[(r0+8) *LDT + kcol + 8];
                aL[mf][0] = *(const uint32_t*)&AsL[ r0    *LDT + kcol    ];
                aL[mf][1] = *(const uint32_t*)&AsL[(r0+8) *LDT + kcol    ];
                aL[mf][2] = *(const uint32_t*)&AsL[ r0    *LDT + kcol + 8];
                aL[mf][3] = *(const uint32_t*)&AsL[(r0+8) *LDT + kcol + 8];
            }
            #pragma unroll
            for (int nf = 0; nf < 8; nf++) {
                int n = wn*64 + nf*8 + g;
                int kr = kb + tq*2;
                uint32_t bH0 = *(const uint32_t*)&BsH[n*LDT + kr    ];
                uint32_t bH1 = *(const uint32_t*)&BsH[n*LDT + kr + 8];
                uint32_t bL0 = *(const uint32_t*)&BsL[n*LDT + kr    ];
                uint32_t bL1 = *(const uint32_t*)&BsL[n*LDT + kr + 8];
                #pragma unroll
                for (int mf = 0; mf < 2; mf++) {
                    MMA_B16(acc[mf][nf], aH[mf], bH0, bH1);
                    MMA_B16(acc[mf][nf], aH[mf], bL0, bL1);
                    MMA_B16(acc[mf][nf], aL[mf], bH0, bH1);
                }
            }
        }
        __syncthreads();
    }

    float gm = (EPI==1 || EPI==3) ? gamma[0] : 0.f;
    float s1 = 0.f, sq = 0.f;
    #pragma unroll
    for (int mf = 0; mf < 2; mf++) {
        int row = m0 + wm*32 + mf*16 + g;
        float bi0 = (EPI!=0) ? bias[row]     : 0.f;
        float bi8 = (EPI!=0) ? bias[row + 8] : 0.f;
        #pragma unroll
        for (int nf = 0; nf < 8; nf++) {
            int col = t0 + wn*64 + nf*8 + tq*2;
            float v00 = acc[mf][nf][0] + bi0;
            float v01 = acc[mf][nf][1] + bi0;
            float v10 = acc[mf][nf][2] + bi8;
            float v11 = acc[mf][nf][3] + bi8;
            size_t i0 = ((size_t)b*MT + row    )*NSP + col;
            size_t i8 = ((size_t)b*MT + row + 8)*NSP + col;
            if (EPI == 2) {
                v00 = v00 / (1.f + __expf(-v00));
                v01 = v01 / (1.f + __expf(-v01));
                v10 = v10 / (1.f + __expf(-v10));
                v11 = v11 / (1.f + __expf(-v11));
            } else if (EPI == 1 || EPI == 3) {
                float2 r0 = *(const float2*)(resid + i0);
                float2 r8 = *(const float2*)(resid + i8);
                v00 = r0.x + gm*v00;  v01 = r0.y + gm*v01;
                v10 = r8.x + gm*v10;  v11 = r8.y + gm*v11;
                if (EPI == 1) {
                    s1 += v00+v01+v10+v11;
                    sq += v00*v00 + v01*v01 + v10*v10 + v11*v11;
                }
            }
            *(float2*)(out + i0) = make_float2(v00, v01);
            *(float2*)(out + i8) = make_float2(v10, v11);
        }
    }
    if (EPI == 1) {
        block_reduce2(s1, sq);
        if (tid == 0) { atomicAdd(&g_sums2[b*2], s1); atomicAdd(&g_sums2[b*2+1], sq); }
    }
}

// ---------- HMMA flash attention ----------
// 4 warps (128 thr); warp w owns queries [w*16, w*16+16). 64-key tiles.
// Q/K staged transposed [row][d], V staged [d][j]. Split-bf16 3-MMA both GEMMs.
#define ALD 66   // bf16 row stride (64 + 2 pad)

__global__ void __launch_bounds__(128) attn_mma(
    const float* __restrict__ qkv, float* __restrict__ outp)
{
    extern __shared__ __nv_bfloat16 smb[];
    __nv_bfloat16* QH = smb;
    __nv_bfloat16* QL = QH + 64*ALD;
    __nv_bfloat16* KH = QL + 64*ALD;
    __nv_bfloat16* KL = KH + 64*ALD;
    __nv_bfloat16* VH = KL + 64*ALD;
    __nv_bfloat16* VL = VH + 64*ALD;

    int it = blockIdx.x, h = blockIdx.y, b = blockIdx.z;
    int tid = threadIdx.x, lane = tid & 31, w = tid >> 5;
    int g = lane >> 2, tq = lane & 3;
    int q0 = w * 16;

    const float* qb = qkv + ((size_t)b*3*CCH +          h*DKD) * NSP + it*64;
    const float* kb = qkv + ((size_t)b*3*CCH +   CCH +  h*DKD) * NSP;
    const float* vb = qkv + ((size_t)b*3*CCH + 2*CCH +  h*DKD) * NSP;

    // stage Q transposed [q][d], pre-scaled by 1/8
    {
        int d = tid >> 1, t8 = (tid & 1) * 32;
        const float* p = qb + (size_t)d * NSP + t8;
        #pragma unroll
        for (int j = 0; j < 8; j++) {
            float4 f = *(const float4*)(p + j*4);
            float v4[4] = {f.x, f.y, f.z, f.w};
            #pragma unroll
            for (int e = 0; e < 4; e++) {
                float v = v4[e] * 0.125f;
                __nv_bfloat16 hh, ll; split_bf16(v, hh, ll);
                int q = t8 + j*4 + e;
                QH[q*ALD + d] = hh; QL[q*ALD + d] = ll;
            }
        }
    }

    float m0 = -1e30f, m1 = -1e30f, l0 = 0.f, l1 = 0.f;
    float oacc[8][4] = {};

    for (int kt = 0; kt < 16; kt++) {
        __syncthreads();
        // stage K transposed [key][d]
        {
            int d = tid >> 1, j8 = (tid & 1) * 32;
            const float* p = kb + (size_t)d * NSP + kt*64 + j8;
            #pragma unroll
            for (int j = 0; j < 8; j++) {
                float4 f = *(const float4*)(p + j*4);
                float v4[4] = {f.x, f.y, f.z, f.w};
                #pragma unroll
                for (int e = 0; e < 4; e++) {
                    __nv_bfloat16 hh, ll; split_bf16(v4[e], hh, ll);
                    int jj = j8 + j*4 + e;
                    KH[jj*ALD + d] = hh; KL[jj*ALD + d] = ll;
                }
            }
        }
        // stage V direct [d][j]
        {
            int d = tid >> 1, j8 = (tid & 1) * 32;
            const float* p = vb + (size_t)d * NSP + kt*64 + j8;
            #pragma unroll
            for (int j = 0; j < 8; j++) {
                float4 f = *(const float4*)(p + j*4);
                float v4[4] = {f.x, f.y, f.z, f.w};
                #pragma unroll
                for (int e = 0; e < 4; e++) {
                    __nv_bfloat16 hh, ll; split_bf16(v4[e], hh, ll);
                    VH[d*ALD + j8 + j*4 + e] = hh;
                    VL[d*ALD + j8 + j*4 + e] = ll;
                }
            }
        }
        __syncthreads();

        // S = Q K^T  (16 x 64 per warp)
        float sacc[8][4] = {};
        #pragma unroll
        for (int kc = 0; kc < 4; kc++) {
            int koff = kc*16 + 2*tq;
            uint32_t aH[4], aL[4];
            aH[0] = *(const uint32_t*)&QH[(q0+g  )*ALD + koff    ];
            aH[1] = *(const uint32_t*)&QH[(q0+g+8)*ALD + koff    ];
            aH[2] = *(const uint32_t*)&QH[(q0+g  )*ALD + koff + 8];
            aH[3] = *(const uint32_t*)&QH[(q0+g+8)*ALD + koff + 8];
            aL[0] = *(const uint32_t*)&QL[(q0+g  )*ALD + koff    ];
            aL[1] = *(const uint32_t*)&QL[(q0+g+8)*ALD + koff    ];
            aL[2] = *(const uint32_t*)&QL[(q0+g  )*ALD + koff + 8];
            aL[3] = *(const uint32_t*)&QL[(q0+g+8)*ALD + koff + 8];
            #pragma unroll
            for (int nf = 0; nf < 8; nf++) {
                int kr = (nf*8 + g)*ALD + koff;
                uint32_t bH0 = *(const uint32_t*)&KH[kr    ];
                uint32_t bH1 = *(const uint32_t*)&KH[kr + 8];
                uint32_t bL0 = *(const uint32_t*)&KL[kr    ];
                uint32_t bL1 = *(const uint32_t*)&KL[kr + 8];
                MMA_B16(sacc[nf], aH, bH0, bH1);
                MMA_B16(sacc[nf], aH, bL0, bL1);
                MMA_B16(sacc[nf], aL, bH0, bH1);
            }
        }

        // online softmax (rows q0+g and q0+g+8)
        float rm0 = -1e30f, rm1 = -1e30f;
        #pragma unroll
        for (int nf = 0; nf < 8; nf++) {
            rm0 = fmaxf(rm0, fmaxf(sacc[nf][0], sacc[nf][1]));
            rm1 = fmaxf(rm1, fmaxf(sacc[nf][2], sacc[nf][3]));
        }
        rm0 = fmaxf(rm0, __shfl_xor_sync(0xffffffffu, rm0, 1));
        rm0 = fmaxf(rm0, __shfl_xor_sync(0xffffffffu, rm0, 2));
        rm1 = fmaxf(rm1, __shfl_xor_sync(0xffffffffu, rm1, 1));
        rm1 = fmaxf(rm1, __shfl_xor_sync(0xffffffffu, rm1, 2));
        float mn0 = fmaxf(m0, rm0), mn1 = fmaxf(m1, rm1);
        float al0 = __expf(m0 - mn0), al1 = __expf(m1 - mn1);
        m0 = mn0; m1 = mn1;
        float ls0 = 0.f, ls1 = 0.f;
        #pragma unroll
        for (int nf = 0; nf < 8; nf++) {
            sacc[nf][0] = __expf(sacc[nf][0] - mn0);
            sacc[nf][1] = __expf(sacc[nf][1] - mn0);
            sacc[nf][2] = __expf(sacc[nf][2] - mn1);
            sacc[nf][3] = __expf(sacc[nf][3] - mn1);
            ls0 += sacc[nf][0] + sacc[nf][1];
            ls1 += sacc[nf][2] + sacc[nf][3];
        }
        ls0 += __shfl_xor_sync(0xffffffffu, ls0, 1);
        ls0 += __shfl_xor_sync(0xffffffffu, ls0, 2);
        ls1 += __shfl_xor_sync(0xffffffffu, ls1, 1);
        ls1 += __shfl_xor_sync(0xffffffffu, ls1, 2);
        l0 = l0 * al0 + ls0;
        l1 = l1 * al1 + ls1;
        #pragma unroll
        for (int nf = 0; nf < 8; nf++) {
            oacc[nf][0] *= al0; oacc[nf][1] *= al0;
            oacc[nf][2] *= al1; oacc[nf][3] *= al1;
        }

        // P fragments in registers (S acc layout == A-operand layout)
        uint32_t pH[4][4], pL[4][4];
        #pragma unroll
        for (int c = 0; c < 4; c++) {
            pack2(sacc[2*c  ][0], sacc[2*c  ][1], pH[c][0], pL[c][0]);
            pack2(sacc[2*c  ][2], sacc[2*c  ][3], pH[c][1], pL[c][1]);
            pack2(sacc[2*c+1][0], sacc[2*c+1][1], pH[c][2], pL[c][2]);
            pack2(sacc[2*c+1][2], sacc[2*c+1][3], pH[c][3], pL[c][3]);
        }

        // O += P V  (16 x 64 per warp)
        #pragma unroll
        for (int c = 0; c < 4; c++) {
            int joff = c*16 + 2*tq;
            #pragma unroll
            for (int nf = 0; nf < 8; nf++) {
                int vr = (nf*8 + g)*ALD + joff;
                uint32_t bH0 = *(const uint32_t*)&VH[vr    ];
                uint32_t bH1 = *(const uint32_t*)&VH[vr + 8];
                uint32_t bL0 = *(const uint32_t*)&VL[vr    ];
                uint32_t bL1 = *(const uint32_t*)&VL[vr + 8];
                MMA_B16(oacc[nf], pH[c], bH0, bH1);
                MMA_B16(oacc[nf], pH[c], bL0, bL1);
                MMA_B16(oacc[nf], pL[c], bH0, bH1);
            }
        }
    }

    // finalize: transpose via smem (overlay dead Q tiles), coalesced writes
    __syncthreads();
    float inv0 = 1.f / l0, inv1 = 1.f / l1;
    float* OS = (float*)smb;   // [d][q], stride 64 (16384 B <= QH+QL区 16896 B)
    #pragma unroll
    for (int nf = 0; nf < 8; nf++) {
        int d = nf*8 + 2*tq;
        OS[(d  )*64 + q0 + g    ] = oacc[nf][0] * inv0;
        OS[(d+1)*64 + q0 + g    ] = oacc[nf][1] * inv0;
        OS[(d  )*64 + q0 + g + 8] = oacc[nf][2] * inv1;
        OS[(d+1)*64 + q0 + g + 8] = oacc[nf][3] * inv1;
    }
    __syncthreads();
    {
        int d = tid >> 1, q8 = (tid & 1) * 32;
        float* ob = outp + ((size_t)b*CCH + h*DKD + d)*NSP + it*64 + q8;
        #pragma unroll
        for (int j = 0; j < 8; j++)
            *(float4*)(ob + j*4) = *(const float4*)&OS[d*64 + q8 + j*4];
    }
}

// ---------- launch ----------
#define ATTN_SMEM (6*64*ALD*2)

extern "C" void kernel_launch(void* const* d_in, const int* in_sizes, int n_in,
                              void* d_out, int out_size) {
    const float* x     = (const float*)d_in[0];
    const float* qkv_w = (const float*)d_in[1];
    const float* uh_w  = (const float*)d_in[2];
    const float* uh_b  = (const float*)d_in[3];
    const float* n1_w  = (const float*)d_in[4];
    const float* n1_b  = (const float*)d_in[5];
    const float* n2_w  = (const float*)d_in[6];
    const float* n2_b  = (const float*)d_in[7];
    const float* f1_w  = (const float*)d_in[8];
    const float* f1_b  = (const float*)d_in[9];
    const float* f2_w  = (const float*)d_in[10];
    const float* f2_b  = (const float*)d_in[11];
    const float* g_at  = (const float*)d_in[12];
    const float* g_ff  = (const float*)d_in[13];
    float* out = (float*)d_out;

    float *qkv_buf, *attn_buf, *x2_buf, *h1_buf;
    cudaGetSymbolAddress((void**)&qkv_buf,  g_qkv);
    cudaGetSymbolAddress((void**)&attn_buf, g_attn);
    cudaGetSymbolAddress((void**)&x2_buf,   g_x2);
    cudaGetSymbolAddress((void**)&h1_buf,   g_h1);

    cudaFuncSetAttribute(attn_mma, cudaFuncAttributeMaxDynamicSharedMemorySize, ATTN_SMEM);

    zero_stats_kernel<<<1, 32>>>();
    gn_stats_kernel<<<dim3(32, BSZ), 256>>>(x);

    // qkv = qkv_w @ GN1(x)
    gemm_mma<256,1,0><<<dim3(8,6,BSZ), 256>>>(
        x, qkv_w, n1_w, n1_b, nullptr, nullptr, nullptr, qkv_buf);

    attn_mma<<<dim3(16, NHH, BSZ), 128, ATTN_SMEM>>>(qkv_buf, attn_buf);

    // x2 = x + g_at*(uh_w@attn + uh_b), + GN2 stats
    gemm_mma<256,0,1><<<dim3(8,2,BSZ), 256>>>(
        attn_buf, uh_w, nullptr, nullptr, uh_b, x, g_at, x2_buf);

    // h1 = silu(f1_w @ GN2(x2) + f1_b)
    gemm_mma<256,2,2><<<dim3(8,8,BSZ), 256>>>(
        x2_buf, f1_w, n2_w, n2_b, f1_b, nullptr, nullptr, h1_buf);

    // out = x2 + g_ff*(f2_w@h1 + f2_b)
    gemm_mma<1024,0,3><<<dim3(8,2,BSZ), 256>>>(
        h1_buf, f2_w, nullptr, nullptr, f2_b, x2_buf, g_ff, out);
}

// round 7
// speedup vs baseline: 1.6322x; 1.2852x over previous
#include <cuda_runtime.h>
#include <cuda_bf16.h>
#include <math.h>
#include <stdint.h>

#define BSZ 8
#define CCH 256
#define NSP 1024
#define NHH 4
#define DKD 64
#define CNT (CCH*NSP)

__device__ float g_sums1[2*BSZ];
__device__ float g_sums2[2*BSZ];
__device__ float g_qkv [(size_t)BSZ*3*CCH*NSP];
__device__ float g_attn[(size_t)BSZ*CCH*NSP];
__device__ float g_x2  [(size_t)BSZ*CCH*NSP];
__device__ float g_h1  [(size_t)BSZ*4*CCH*NSP];

// ---------- reductions / stats ----------
__device__ __forceinline__ void block_reduce2(float& s, float& s2) {
    #pragma unroll
    for (int o = 16; o; o >>= 1) {
        s  += __shfl_xor_sync(0xffffffffu, s,  o);
        s2 += __shfl_xor_sync(0xffffffffu, s2, o);
    }
    __shared__ float sh0[8], sh1[8];
    int w = threadIdx.x >> 5, l = threadIdx.x & 31;
    if (l == 0) { sh0[w] = s; sh1[w] = s2; }
    __syncthreads();
    if (w == 0) {
        s  = (l < 8) ? sh0[l] : 0.f;
        s2 = (l < 8) ? sh1[l] : 0.f;
        #pragma unroll
        for (int o = 4; o; o >>= 1) {
            s  += __shfl_xor_sync(0xffffffffu, s,  o);
            s2 += __shfl_xor_sync(0xffffffffu, s2, o);
        }
    }
}

__global__ void zero_stats_kernel() {
    int t = threadIdx.x;
    if (t < 2*BSZ) { g_sums1[t] = 0.f; g_sums2[t] = 0.f; }
}

__global__ void gn_stats_kernel(const float* __restrict__ x) {
    int b = blockIdx.y;
    const float* xb = x + (size_t)b * CNT;
    int base = blockIdx.x * (CNT / 32);
    float s = 0.f, s2 = 0.f;
    for (int i = threadIdx.x; i < CNT/32; i += 256) {
        float v = xb[base + i];
        s += v; s2 += v*v;
    }
    block_reduce2(s, s2);
    if (threadIdx.x == 0) {
        atomicAdd(&g_sums1[b*2],   s);
        atomicAdd(&g_sums1[b*2+1], s2);
    }
}

// ---------- HMMA helpers ----------
#define MMA_B16(c, a, b0, b1) \
  asm volatile("mma.sync.aligned.m16n8k16.row.col.f32.bf16.bf16.f32 " \
    "{%0,%1,%2,%3}, {%4,%5,%6,%7}, {%8,%9}, {%0,%1,%2,%3};" \
    : "+f"((c)[0]),"+f"((c)[1]),"+f"((c)[2]),"+f"((c)[3]) \
    : "r"((a)[0]),"r"((a)[1]),"r"((a)[2]),"r"((a)[3]), "r"(b0),"r"(b1))

__device__ __forceinline__ void ldsm4(uint32_t& r0, uint32_t& r1, uint32_t& r2,
                                      uint32_t& r3, uint32_t addr) {
    asm volatile("ldmatrix.sync.aligned.m8n8.x4.shared.b16 {%0,%1,%2,%3}, [%4];"
        : "=r"(r0), "=r"(r1), "=r"(r2), "=r"(r3) : "r"(addr));
}
__device__ __forceinline__ uint32_t s2u(const void* p) {
    return (uint32_t)__cvta_generic_to_shared(p);
}
__device__ __forceinline__ void split_bf16(float v, __nv_bfloat16& h, __nv_bfloat16& l) {
    h = __float2bfloat16(v);
    l = __float2bfloat16(v - __bfloat162float(h));
}
__device__ __forceinline__ void pack2(float a, float b, uint32_t& h, uint32_t& l) {
    __nv_bfloat162 hb = __floats2bfloat162_rn(a, b);
    float ra = a - __bfloat162float(hb.x);
    float rb = b - __bfloat162float(hb.y);
    __nv_bfloat162 lb = __floats2bfloat162_rn(ra, rb);
    h = *(uint32_t*)&hb; l = *(uint32_t*)&lb;
}

// ---------- fused HMMA GEMM (unchanged from passing R5/R6) ----------
#define LDT 34

template<int K, int NORMSRC, int EPI>
__global__ void __launch_bounds__(256) gemm_mma(
    const float* __restrict__ Act, const float* __restrict__ W,
    const float* __restrict__ gw, const float* __restrict__ gb,
    const float* __restrict__ bias, const float* __restrict__ resid,
    const float* __restrict__ gamma, float* __restrict__ out)
{
    constexpr int MT = (EPI==0)?768:(EPI==2)?1024:256;
    __shared__ __nv_bfloat16 AsH[128*LDT], AsL[128*LDT];
    __shared__ __nv_bfloat16 BsH[128*LDT], BsL[128*LDT];

    int tid = threadIdx.x, lane = tid & 31, w = tid >> 5;
    int wm = w & 3, wn = w >> 2;
    int t0 = blockIdx.x * 128, m0 = blockIdx.y * 128, b = blockIdx.z;

    float mean = 0.f, rstd = 0.f;
    if (NORMSRC) {
        const float* s = (NORMSRC == 1) ? g_sums1 : g_sums2;
        mean = s[b*2] * (1.f/CNT);
        rstd = rsqrtf(s[b*2+1] * (1.f/CNT) - mean*mean + 1e-5f);
    }

    float acc[2][8][4] = {};
    const int g = lane >> 2, tq = lane & 3;

    for (int c = 0; c < K/32; c++) {
        int kc = c * 32;
        {
            int kk = tid >> 3, tg = (tid & 7) * 16, ch = kc + kk;
            float gwc = NORMSRC ? gw[ch] : 1.f, gbc = NORMSRC ? gb[ch] : 0.f;
            const float* p = Act + ((size_t)b*K + ch)*NSP + t0 + tg;
            #pragma unroll
            for (int j = 0; j < 4; j++) {
                float4 f = *(const float4*)(p + j*4);
                float v4[4] = {f.x, f.y, f.z, f.w};
                #pragma unroll
                for (int e = 0; e < 4; e++) {
                    float v = NORMSRC ? (v4[e]-mean)*rstd*gwc + gbc : v4[e];
                    __nv_bfloat16 h, l; split_bf16(v, h, l);
                    int tok = tg + j*4 + e;
                    BsH[tok*LDT + kk] = h;
                    BsL[tok*LDT + kk] = l;
                }
            }
        }
        {
            int m = tid >> 1, kh = (tid & 1) * 16;
            const float* p = W + (size_t)(m0 + m)*K + kc + kh;
            #pragma unroll
            for (int j = 0; j < 4; j++) {
                float4 f = *(const float4*)(p + j*4);
                float v4[4] = {f.x, f.y, f.z, f.w};
                #pragma unroll
                for (int e = 0; e < 4; e++) {
                    __nv_bfloat16 h, l; split_bf16(v4[e], h, l);
                    AsH[m*LDT + kh + j*4 + e] = h;
                    AsL[m*LDT + kh + j*4 + e] = l;
                }
            }
        }
        __syncthreads();

        #pragma unroll
        for (int ks = 0; ks < 2; ks++) {
            int kb = ks * 16;
            uint32_t aH[2][4], aL[2][4];
            #pragma unroll
            for (int mf = 0; mf < 2; mf++) {
                int r0 = wm*32 + mf*16 + g;
                int kcol = kb + tq*2;
                aH[mf][0] = *(const uint32_t*)&AsH[ r0    *LDT + kcol    ];
                aH[mf][1] = *(const uint32_t*)&AsH[(r0+8) *LDT + kcol    ];
                aH[mf][2] = *(const uint32_t*)&AsH[ r0    *LDT + kcol + 8];
                aH[mf][3] = *(const uint32_t*)&AsH[(r0+8) *LDT + kcol + 8];
                aL[mf][0] = *(const uint32_t*)&AsL[ r0    *LDT + kcol    ];
                aL[mf][1] = *(const uint32_t*)&AsL[(r0+8) *LDT + kcol    ];
                aL[mf][2] = *(const uint32_t*)&AsL[ r0    *LDT + kcol + 8];
                aL[mf][3] = *(const uint32_t*)&AsL[(r0+8) *LDT + kcol + 8];
            }
            #pragma unroll
            for (int nf = 0; nf < 8; nf++) {
                int n = wn*64 + nf*8 + g;
                int kr = kb + tq*2;
                uint32_t bH0 = *(const uint32_t*)&BsH[n*LDT + kr    ];
                uint32_t bH1 = *(const uint32_t*)&BsH[n*LDT + kr + 8];
                uint32_t bL0 = *(const uint32_t*)&BsL[n*LDT + kr    ];
                uint32_t bL1 = *(const uint32_t*)&BsL[n*LDT + kr + 8];
                #pragma unroll
                for (int mf = 0; mf < 2; mf++) {
                    MMA_B16(acc[mf][nf], aH[mf], bH0, bH1);
                    MMA_B16(acc[mf][nf], aH[mf], bL0, bL1);
                    MMA_B16(acc[mf][nf], aL[mf], bH0, bH1);
                }
            }
        }
        __syncthreads();
    }

    float gm = (EPI==1 || EPI==3) ? gamma[0] : 0.f;
    float s1 = 0.f, sq = 0.f;
    #pragma unroll
    for (int mf = 0; mf < 2; mf++) {
        int row = m0 + wm*32 + mf*16 + g;
        float bi0 = (EPI!=0) ? bias[row]     : 0.f;
        float bi8 = (EPI!=0) ? bias[row + 8] : 0.f;
        #pragma unroll
        for (int nf = 0; nf < 8; nf++) {
            int col = t0 + wn*64 + nf*8 + tq*2;
            float v00 = acc[mf][nf][0] + bi0;
            float v01 = acc[mf][nf][1] + bi0;
            float v10 = acc[mf][nf][2] + bi8;
            float v11 = acc[mf][nf][3] + bi8;
            size_t i0 = ((size_t)b*MT + row    )*NSP + col;
            size_t i8 = ((size_t)b*MT + row + 8)*NSP + col;
            if (EPI == 2) {
                v00 = v00 / (1.f + __expf(-v00));
                v01 = v01 / (1.f + __expf(-v01));
                v10 = v10 / (1.f + __expf(-v10));
                v11 = v11 / (1.f + __expf(-v11));
            } else if (EPI == 1 || EPI == 3) {
                float2 r0 = *(const float2*)(resid + i0);
                float2 r8 = *(const float2*)(resid + i8);
                v00 = r0.x + gm*v00;  v01 = r0.y + gm*v01;
                v10 = r8.x + gm*v10;  v11 = r8.y + gm*v11;
                if (EPI == 1) {
                    s1 += v00+v01+v10+v11;
                    sq += v00*v00 + v01*v01 + v10*v10 + v11*v11;
                }
            }
            *(float2*)(out + i0) = make_float2(v00, v01);
            *(float2*)(out + i8) = make_float2(v10, v11);
        }
    }
    if (EPI == 1) {
        block_reduce2(s1, sq);
        if (tid == 0) { atomicAdd(&g_sums2[b*2], s1); atomicAdd(&g_sums2[b*2+1], sq); }
    }
}

// ---------- HMMA flash attention, ldmatrix + packed staging ----------
#define ALD 72   // bf16 row stride: 144 B rows, 16B-aligned, conflict-free ldmatrix

__global__ void __launch_bounds__(128) attn_mma(
    const float* __restrict__ qkv, float* __restrict__ outp)
{
    extern __shared__ __nv_bfloat16 smb[];
    __nv_bfloat16* QH = smb;
    __nv_bfloat16* QL = QH + 64*ALD;
    __nv_bfloat16* KH = QL + 64*ALD;
    __nv_bfloat16* KL = KH + 64*ALD;
    __nv_bfloat16* VH = KL + 64*ALD;
    __nv_bfloat16* VL = VH + 64*ALD;

    int it = blockIdx.x, h = blockIdx.y, b = blockIdx.z;
    int tid = threadIdx.x, lane = tid & 31, w = tid >> 5;
    int g = lane >> 2, tq = lane & 3;
    int q0 = w * 16;

    const float* qb = qkv + ((size_t)b*3*CCH +          h*DKD) * NSP + it*64;
    const float* kb = qkv + ((size_t)b*3*CCH +   CCH +  h*DKD) * NSP;
    const float* vb = qkv + ((size_t)b*3*CCH + 2*CCH +  h*DKD) * NSP;

    // ldmatrix per-lane base offsets (byte offsets into a [row][64] tile)
    const int lrow = lane & 7, lt = lane >> 3;
    // A tiles: t0=(rows0-7,k0) t1=(rows8-15,k0) t2=(rows0-7,k8) t3=(rows8-15,k8)
    const uint32_t a_off = (uint32_t)((q0 + ((lt & 1) << 3) + lrow) * (ALD*2) + (lt >> 1) * 16);
    // B tiles: t0=(rows0-7,k0) t1=(rows0-7,k8) t2=(rows8-15,k0) t3=(rows8-15,k8)
    const uint32_t b_off = (uint32_t)((((lt >> 1) << 3) + lrow) * (ALD*2) + (lt & 1) * 16);
    const uint32_t uQH = s2u(QH), uQL = s2u(QL);
    const uint32_t uKH = s2u(KH), uKL = s2u(KL);
    const uint32_t uVH = s2u(VH), uVL = s2u(VL);

    // stage Q: thread owns d-pair (2dp,2dp+1) x 16 queries; bf16x2 STS.32
    {
        int dp = tid >> 2, kg = tid & 3;
        const float* p0 = qb + (size_t)(2*dp) * NSP + kg*16;
        const float* p1 = p0 + NSP;
        #pragma unroll
        for (int qd = 0; qd < 4; qd++) {
            float4 fa = *(const float4*)(p0 + qd*4);
            float4 fb = *(const float4*)(p1 + qd*4);
            float va[4] = {fa.x, fa.y, fa.z, fa.w};
            float vbb[4] = {fb.x, fb.y, fb.z, fb.w};
            #pragma unroll
            for (int e = 0; e < 4; e++) {
                int qq = kg*16 + qd*4 + e;
                uint32_t H, L;
                pack2(va[e]*0.125f, vbb[e]*0.125f, H, L);
                *(uint32_t*)&QH[qq*ALD + 2*dp] = H;
                *(uint32_t*)&QL[qq*ALD + 2*dp] = L;
            }
        }
    }

    float m0 = -1e30f, m1 = -1e30f, l0 = 0.f, l1 = 0.f;
    float oacc[8][4] = {};

    for (int kt = 0; kt < 16; kt++) {
        __syncthreads();
        // stage K: [key][d], d-pairs packed, STS.32
        {
            int dp = tid >> 2, kg = tid & 3;
            const float* p0 = kb + (size_t)(2*dp) * NSP + kt*64 + kg*16;
            const float* p1 = p0 + NSP;
            #pragma unroll
            for (int qd = 0; qd < 4; qd++) {
                float4 fa = *(const float4*)(p0 + qd*4);
                float4 fb = *(const float4*)(p1 + qd*4);
                float va[4] = {fa.x, fa.y, fa.z, fa.w};
                float vbb[4] = {fb.x, fb.y, fb.z, fb.w};
                #pragma unroll
                for (int e = 0; e < 4; e++) {
                    int key = kg*16 + qd*4 + e;
                    uint32_t H, L;
                    pack2(va[e], vbb[e], H, L);
                    *(uint32_t*)&KH[key*ALD + 2*dp] = H;
                    *(uint32_t*)&KL[key*ALD + 2*dp] = L;
                }
            }
        }
        // stage V: [d][j], contiguous j, STS.128
        {
            int d = tid >> 1, j8 = (tid & 1) * 32;
            const float* p = vb + (size_t)d * NSP + kt*64 + j8;
            #pragma unroll
            for (int qd = 0; qd < 4; qd++) {
                float4 fa = *(const float4*)(p + qd*8);
                float4 fb = *(const float4*)(p + qd*8 + 4);
                float f[8] = {fa.x, fa.y, fa.z, fa.w, fb.x, fb.y, fb.z, fb.w};
                uint32_t H[4], L[4];
                #pragma unroll
                for (int e = 0; e < 4; e++) pack2(f[2*e], f[2*e+1], H[e], L[e]);
                *(uint4*)&VH[d*ALD + j8 + qd*8] = make_uint4(H[0], H[1], H[2], H[3]);
                *(uint4*)&VL[d*ALD + j8 + qd*8] = make_uint4(L[0], L[1], L[2], L[3]);
            }
        }
        __syncthreads();

        // S = Q K^T (16 x 64 per warp), split-bf16 3-MMA
        float sacc[8][4] = {};
        #pragma unroll
        for (int kc = 0; kc < 4; kc++) {
            uint32_t aH[4], aL[4];
            ldsm4(aH[0], aH[1], aH[2], aH[3], uQH + a_off + kc*32);
            ldsm4(aL[0], aL[1], aL[2], aL[3], uQL + a_off + kc*32);
            #pragma unroll
            for (int p = 0; p < 4; p++) {
                uint32_t h0, h1, h2, h3, x0, x1, x2, x3;
                ldsm4(h0, h1, h2, h3, uKH + b_off + p*16*(ALD*2) + kc*32);
                ldsm4(x0, x1, x2, x3, uKL + b_off + p*16*(ALD*2) + kc*32);
                MMA_B16(sacc[2*p  ], aH, h0, h1);
                MMA_B16(sacc[2*p  ], aH, x0, x1);
                MMA_B16(sacc[2*p  ], aL, h0, h1);
                MMA_B16(sacc[2*p+1], aH, h2, h3);
                MMA_B16(sacc[2*p+1], aH, x2, x3);
                MMA_B16(sacc[2*p+1], aL, h2, h3);
            }
        }

        // online softmax (rows q0+g and q0+g+8)
        float rm0 = -1e30f, rm1 = -1e30f;
        #pragma unroll
        for (int nf = 0; nf < 8; nf++) {
            rm0 = fmaxf(rm0, fmaxf(sacc[nf][0], sacc[nf][1]));
            rm1 = fmaxf(rm1, fmaxf(sacc[nf][2], sacc[nf][3]));
        }
        rm0 = fmaxf(rm0, __shfl_xor_sync(0xffffffffu, rm0, 1));
        rm0 = fmaxf(rm0, __shfl_xor_sync(0xffffffffu, rm0, 2));
        rm1 = fmaxf(rm1, __shfl_xor_sync(0xffffffffu, rm1, 1));
        rm1 = fmaxf(rm1, __shfl_xor_sync(0xffffffffu, rm1, 2));
        float mn0 = fmaxf(m0, rm0), mn1 = fmaxf(m1, rm1);
        float al0 = __expf(m0 - mn0), al1 = __expf(m1 - mn1);
        m0 = mn0; m1 = mn1;
        float ls0 = 0.f, ls1 = 0.f;
        #pragma unroll
        for (int nf = 0; nf < 8; nf++) {
            sacc[nf][0] = __expf(sacc[nf][0] - mn0);
            sacc[nf][1] = __expf(sacc[nf][1] - mn0);
            sacc[nf][2] = __expf(sacc[nf][2] - mn1);
            sacc[nf][3] = __expf(sacc[nf][3] - mn1);
            ls0 += sacc[nf][0] + sacc[nf][1];
            ls1 += sacc[nf][2] + sacc[nf][3];
        }
        ls0 += __shfl_xor_sync(0xffffffffu, ls0, 1);
        ls0 += __shfl_xor_sync(0xffffffffu, ls0, 2);
        ls1 += __shfl_xor_sync(0xffffffffu, ls1, 1);
        ls1 += __shfl_xor_sync(0xffffffffu, ls1, 2);
        l0 = l0 * al0 + ls0;
        l1 = l1 * al1 + ls1;
        #pragma unroll
        for (int nf = 0; nf < 8; nf++) {
            oacc[nf][0] *= al0; oacc[nf][1] *= al0;
            oacc[nf][2] *= al1; oacc[nf][3] *= al1;
        }

        // P fragments in registers (S acc layout == A-operand layout)
        uint32_t pH[4][4], pL[4][4];
        #pragma unroll
        for (int c = 0; c < 4; c++) {
            pack2(sacc[2*c  ][0], sacc[2*c  ][1], pH[c][0], pL[c][0]);
            pack2(sacc[2*c  ][2], sacc[2*c  ][3], pH[c][1], pL[c][1]);
            pack2(sacc[2*c+1][0], sacc[2*c+1][1], pH[c][2], pL[c][2]);
            pack2(sacc[2*c+1][2], sacc[2*c+1][3], pH[c][3], pL[c][3]);
        }

        // O += P V (16 x 64 per warp)
        #pragma unroll
        for (int c = 0; c < 4; c++) {
            #pragma unroll
            for (int p = 0; p < 4; p++) {
                uint32_t h0, h1, h2, h3, x0, x1, x2, x3;
                ldsm4(h0, h1, h2, h3, uVH + b_off + p*16*(ALD*2) + c*32);
                ldsm4(x0, x1, x2, x3, uVL + b_off + p*16*(ALD*2) + c*32);
                MMA_B16(oacc[2*p  ], pH[c], h0, h1);
                MMA_B16(oacc[2*p  ], pH[c], x0, x1);
                MMA_B16(oacc[2*p  ], pL[c], h0, h1);
                MMA_B16(oacc[2*p+1], pH[c], h2, h3);
                MMA_B16(oacc[2*p+1], pH[c], x2, x3);
                MMA_B16(oacc[2*p+1], pL[c], h2, h3);
            }
        }
    }

    // finalize: transpose via smem (overlay dead Q tiles), coalesced writes
    __syncthreads();
    float inv0 = 1.f / l0, inv1 = 1.f / l1;
    float* OS = (float*)smb;   // [d][q], stride 64 floats; 16 KB <= Q region 18.4 KB
    #pragma unroll
    for (int nf = 0; nf < 8; nf++) {
        int d = nf*8 + 2*tq;
        OS[(d  )*64 + q0 + g    ] = oacc[nf][0] * inv0;
        OS[(d+1)*64 + q0 + g    ] = oacc[nf][1] * inv0;
        OS[(d  )*64 + q0 + g + 8] = oacc[nf][2] * inv1;
        OS[(d+1)*64 + q0 + g + 8] = oacc[nf][3] * inv1;
    }
    __syncthreads();
    {
        int d = tid >> 1, q8 = (tid & 1) * 32;
        float* ob = outp + ((size_t)b*CCH + h*DKD + d)*NSP + it*64 + q8;
        #pragma unroll
        for (int j = 0; j < 8; j++)
            *(float4*)(ob + j*4) = *(const float4*)&OS[d*64 + q8 + j*4];
    }
}

// ---------- launch ----------
#define ATTN_SMEM (6*64*ALD*2)

extern "C" void kernel_launch(void* const* d_in, const int* in_sizes, int n_in,
                              void* d_out, int out_size) {
    const float* x     = (const float*)d_in[0];
    const float* qkv_w = (const float*)d_in[1];
    const float* uh_w  = (const float*)d_in[2];
    const float* uh_b  = (const float*)d_in[3];
    const float* n1_w  = (const float*)d_in[4];
    const float* n1_b  = (const float*)d_in[5];
    const float* n2_w  = (const float*)d_in[6];
    const float* n2_b  = (const float*)d_in[7];
    const float* f1_w  = (const float*)d_in[8];
    const float* f1_b  = (const float*)d_in[9];
    const float* f2_w  = (const float*)d_in[10];
    const float* f2_b  = (const float*)d_in[11];
    const float* g_at  = (const float*)d_in[12];
    const float* g_ff  = (const float*)d_in[13];
    float* out = (float*)d_out;

    float *qkv_buf, *attn_buf, *x2_buf, *h1_buf;
    cudaGetSymbolAddress((void**)&qkv_buf,  g_qkv);
    cudaGetSymbolAddress((void**)&attn_buf, g_attn);
    cudaGetSymbolAddress((void**)&x2_buf,   g_x2);
    cudaGetSymbolAddress((void**)&h1_buf,   g_h1);

    cudaFuncSetAttribute(attn_mma, cudaFuncAttributeMaxDynamicSharedMemorySize, ATTN_SMEM);

    zero_stats_kernel<<<1, 32>>>();
    gn_stats_kernel<<<dim3(32, BSZ), 256>>>(x);

    // qkv = qkv_w @ GN1(x)
    gemm_mma<256,1,0><<<dim3(8,6,BSZ), 256>>>(
        x, qkv_w, n1_w, n1_b, nullptr, nullptr, nullptr, qkv_buf);

    attn_mma<<<dim3(16, NHH, BSZ), 128, ATTN_SMEM>>>(qkv_buf, attn_buf);

    // x2 = x + g_at*(uh_w@attn + uh_b), + GN2 stats
    gemm_mma<256,0,1><<<dim3(8,2,BSZ), 256>>>(
        attn_buf, uh_w, nullptr, nullptr, uh_b, x, g_at, x2_buf);

    // h1 = silu(f1_w @ GN2(x2) + f1_b)
    gemm_mma<256,2,2><<<dim3(8,8,BSZ), 256>>>(
        x2_buf, f1_w, n2_w, n2_b, f1_b, nullptr, nullptr, h1_buf);

    // out = x2 + g_ff*(f2_w@h1 + f2_b)
    gemm_mma<1024,0,3><<<dim3(8,2,BSZ), 256>>>(
        h1_buf, f2_w, nullptr, nullptr, f2_b, x2_buf, g_ff, out);
}

// round 8
// speedup vs baseline: 1.8254x; 1.1184x over previous
#include <cuda_runtime.h>
#include <cuda_bf16.h>
#include <math.h>
#include <stdint.h>

#define BSZ 8
#define CCH 256
#define NSP 1024
#define NHH 4
#define DKD 64
#define CNT (CCH*NSP)

__device__ float g_sums1[2*BSZ];
__device__ float g_sums2[2*BSZ];
__device__ float g_qkv [(size_t)BSZ*3*CCH*NSP];
__device__ float g_attn[(size_t)BSZ*CCH*NSP];
__device__ float g_x2  [(size_t)BSZ*CCH*NSP];
__device__ float g_h1  [(size_t)BSZ*4*CCH*NSP];

// ---------- reductions / stats ----------
__device__ __forceinline__ void block_reduce2(float& s, float& s2) {
    #pragma unroll
    for (int o = 16; o; o >>= 1) {
        s  += __shfl_xor_sync(0xffffffffu, s,  o);
        s2 += __shfl_xor_sync(0xffffffffu, s2, o);
    }
    __shared__ float sh0[8], sh1[8];
    int w = threadIdx.x >> 5, l = threadIdx.x & 31;
    if (l == 0) { sh0[w] = s; sh1[w] = s2; }
    __syncthreads();
    if (w == 0) {
        s  = (l < 8) ? sh0[l] : 0.f;
        s2 = (l < 8) ? sh1[l] : 0.f;
        #pragma unroll
        for (int o = 4; o; o >>= 1) {
            s  += __shfl_xor_sync(0xffffffffu, s,  o);
            s2 += __shfl_xor_sync(0xffffffffu, s2, o);
        }
    }
}

__global__ void zero_stats_kernel() {
    int t = threadIdx.x;
    if (t < 2*BSZ) { g_sums1[t] = 0.f; g_sums2[t] = 0.f; }
}

__global__ void gn_stats_kernel(const float* __restrict__ x) {
    int b = blockIdx.y;
    const float* xb = x + (size_t)b * CNT;
    int base = blockIdx.x * (CNT / 32);
    float s = 0.f, s2 = 0.f;
    for (int i = threadIdx.x; i < CNT/32; i += 256) {
        float v = xb[base + i];
        s += v; s2 += v*v;
    }
    block_reduce2(s, s2);
    if (threadIdx.x == 0) {
        atomicAdd(&g_sums1[b*2],   s);
        atomicAdd(&g_sums1[b*2+1], s2);
    }
}

// ---------- HMMA helpers ----------
#define MMA_B16(c, a, b0, b1) \
  asm volatile("mma.sync.aligned.m16n8k16.row.col.f32.bf16.bf16.f32 " \
    "{%0,%1,%2,%3}, {%4,%5,%6,%7}, {%8,%9}, {%0,%1,%2,%3};" \
    : "+f"((c)[0]),"+f"((c)[1]),"+f"((c)[2]),"+f"((c)[3]) \
    : "r"((a)[0]),"r"((a)[1]),"r"((a)[2]),"r"((a)[3]), "r"(b0),"r"(b1))

__device__ __forceinline__ void ldsm4(uint32_t& r0, uint32_t& r1, uint32_t& r2,
                                      uint32_t& r3, uint32_t addr) {
    asm volatile("ldmatrix.sync.aligned.m8n8.x4.shared.b16 {%0,%1,%2,%3}, [%4];"
        : "=r"(r0), "=r"(r1), "=r"(r2), "=r"(r3) : "r"(addr));
}
__device__ __forceinline__ uint32_t s2u(const void* p) {
    return (uint32_t)__cvta_generic_to_shared(p);
}
__device__ __forceinline__ void pack2(float a, float b, uint32_t& h, uint32_t& l) {
    __nv_bfloat162 hb = __floats2bfloat162_rn(a, b);
    float ra = a - __bfloat162float(hb.x);
    float rb = b - __bfloat162float(hb.y);
    __nv_bfloat162 lb = __floats2bfloat162_rn(ra, rb);
    h = *(uint32_t*)&hb; l = *(uint32_t*)&lb;
}

#define ALD 72   // bf16 row stride: 144 B rows, 16B-aligned, conflict-free ldmatrix

// ---------- fused HMMA GEMM, ldmatrix + packed staging ----------
// D[ch 128, tok 128] = W[m0..m0+128, K] @ Act'[K, tok]; Act channel-major
// EPI: 0 plain(qkv) 1 bias+resid*g+stats(x2) 2 bias+silu(h1) 3 bias+resid*g(final)
template<int K, int NORMSRC, int EPI>
__global__ void __launch_bounds__(256) gemm_mma(
    const float* __restrict__ Act, const float* __restrict__ W,
    const float* __restrict__ gw, const float* __restrict__ gb,
    const float* __restrict__ bias, const float* __restrict__ resid,
    const float* __restrict__ gamma, float* __restrict__ out)
{
    constexpr int MT = (EPI==0)?768:(EPI==2)?1024:256;
    extern __shared__ __nv_bfloat16 smg[];
    __nv_bfloat16* AsH = smg;                 // weights hi [m][k]
    __nv_bfloat16* AsL = AsH + 128*ALD;
    __nv_bfloat16* BsH = AsL + 128*ALD;       // acts hi [tok][k]
    __nv_bfloat16* BsL = BsH + 128*ALD;

    int tid = threadIdx.x, lane = tid & 31, w = tid >> 5;
    int wm = w & 3, wn = w >> 2;
    int t0 = blockIdx.x * 128, m0 = blockIdx.y * 128, b = blockIdx.z;

    float mean = 0.f, rstd = 0.f;
    if (NORMSRC) {
        const float* s = (NORMSRC == 1) ? g_sums1 : g_sums2;
        mean = s[b*2] * (1.f/CNT);
        rstd = rsqrtf(s[b*2+1] * (1.f/CNT) - mean*mean + 1e-5f);
    }

    float acc[2][8][4] = {};
    const int g = lane >> 2, tq = lane & 3;
    const int lrow = lane & 7, lt = lane >> 3;
    // ldmatrix offsets (proven in attention kernel)
    const uint32_t a_off = (uint32_t)((wm*32 + ((lt & 1) << 3) + lrow) * (ALD*2) + (lt >> 1) * 16);
    const uint32_t b_off = (uint32_t)(((wn*64) + ((lt >> 1) << 3) + lrow) * (ALD*2) + (lt & 1) * 16);
    const uint32_t uAH = s2u(AsH), uAL = s2u(AsL);
    const uint32_t uBH = s2u(BsH), uBL = s2u(BsL);

    // staging coords
    const int sm_m = tid >> 1, sm_kh = (tid & 1) * 32;     // weights
    const int sdp = tid & 31, stg = tid >> 5;              // acts: ch pair 2*sdp, tokens stg*16

    for (int c = 0; c < K/64; c++) {
        int kc = c * 64;
        // ---- stage weights: pack2 + STS.128 ----
        {
            const float* p = W + (size_t)(m0 + sm_m)*K + kc + sm_kh;
            #pragma unroll
            for (int qd = 0; qd < 4; qd++) {
                float4 fa = *(const float4*)(p + qd*8);
                float4 fb = *(const float4*)(p + qd*8 + 4);
                float f[8] = {fa.x, fa.y, fa.z, fa.w, fb.x, fb.y, fb.z, fb.w};
                uint32_t H[4], L[4];
                #pragma unroll
                for (int e = 0; e < 4; e++) pack2(f[2*e], f[2*e+1], H[e], L[e]);
                *(uint4*)&AsH[sm_m*ALD + sm_kh + qd*8] = make_uint4(H[0], H[1], H[2], H[3]);
                *(uint4*)&AsL[sm_m*ALD + sm_kh + qd*8] = make_uint4(L[0], L[1], L[2], L[3]);
            }
        }
        // ---- stage activations: transpose, GN fused, packed STS.32 (bank-clean) ----
        {
            int ch = kc + 2*sdp;
            float gw0 = 1.f, gb0 = 0.f, gw1 = 1.f, gb1 = 0.f;
            if (NORMSRC) { gw0 = gw[ch]*rstd; gb0 = gb[ch] - mean*gw0;
                           gw1 = gw[ch+1]*rstd; gb1 = gb[ch+1] - mean*gw1; }
            const float* p0 = Act + ((size_t)b*K + ch)*NSP + t0 + stg*16;
            const float* p1 = p0 + NSP;
            #pragma unroll
            for (int qd = 0; qd < 4; qd++) {
                float4 fa = *(const float4*)(p0 + qd*4);
                float4 fb = *(const float4*)(p1 + qd*4);
                float va[4] = {fa.x, fa.y, fa.z, fa.w};
                float vbb[4] = {fb.x, fb.y, fb.z, fb.w};
                #pragma unroll
                for (int e = 0; e < 4; e++) {
                    float v0 = NORMSRC ? va[e]*gw0 + gb0 : va[e];
                    float v1 = NORMSRC ? vbb[e]*gw1 + gb1 : vbb[e];
                    int tok = stg*16 + qd*4 + e;
                    uint32_t H, L;
                    pack2(v0, v1, H, L);
                    *(uint32_t*)&BsH[tok*ALD + 2*sdp] = H;
                    *(uint32_t*)&BsL[tok*ALD + 2*sdp] = L;
                }
            }
        }
        __syncthreads();

        #pragma unroll
        for (int k4 = 0; k4 < 4; k4++) {
            uint32_t aH[2][4], aL[2][4];
            #pragma unroll
            for (int mf = 0; mf < 2; mf++) {
                ldsm4(aH[mf][0], aH[mf][1], aH[mf][2], aH[mf][3],
                      uAH + a_off + mf*16*(ALD*2) + k4*32);
                ldsm4(aL[mf][0], aL[mf][1], aL[mf][2], aL[mf][3],
                      uAL + a_off + mf*16*(ALD*2) + k4*32);
            }
            #pragma unroll
            for (int p = 0; p < 4; p++) {
                uint32_t h0, h1, h2, h3, x0, x1, x2, x3;
                ldsm4(h0, h1, h2, h3, uBH + b_off + p*16*(ALD*2) + k4*32);
                ldsm4(x0, x1, x2, x3, uBL + b_off + p*16*(ALD*2) + k4*32);
                #pragma unroll
                for (int mf = 0; mf < 2; mf++) {
                    MMA_B16(acc[mf][2*p  ], aH[mf], h0, h1);
                    MMA_B16(acc[mf][2*p  ], aH[mf], x0, x1);
                    MMA_B16(acc[mf][2*p  ], aL[mf], h0, h1);
                    MMA_B16(acc[mf][2*p+1], aH[mf], h2, h3);
                    MMA_B16(acc[mf][2*p+1], aH[mf], x2, x3);
                    MMA_B16(acc[mf][2*p+1], aL[mf], h2, h3);
                }
            }
        }
        __syncthreads();
    }

    // ---- epilogue (fragment layout unchanged) ----
    float gm = (EPI==1 || EPI==3) ? gamma[0] : 0.f;
    float s1 = 0.f, sq = 0.f;
    #pragma unroll
    for (int mf = 0; mf < 2; mf++) {
        int row = m0 + wm*32 + mf*16 + g;
        float bi0 = (EPI!=0) ? bias[row]     : 0.f;
        float bi8 = (EPI!=0) ? bias[row + 8] : 0.f;
        #pragma unroll
        for (int nf = 0; nf < 8; nf++) {
            int col = t0 + wn*64 + nf*8 + tq*2;
            float v00 = acc[mf][nf][0] + bi0;
            float v01 = acc[mf][nf][1] + bi0;
            float v10 = acc[mf][nf][2] + bi8;
            float v11 = acc[mf][nf][3] + bi8;
            size_t i0 = ((size_t)b*MT + row    )*NSP + col;
            size_t i8 = ((size_t)b*MT + row + 8)*NSP + col;
            if (EPI == 2) {
                v00 = v00 / (1.f + __expf(-v00));
                v01 = v01 / (1.f + __expf(-v01));
                v10 = v10 / (1.f + __expf(-v10));
                v11 = v11 / (1.f + __expf(-v11));
            } else if (EPI == 1 || EPI == 3) {
                float2 r0 = *(const float2*)(resid + i0);
                float2 r8 = *(const float2*)(resid + i8);
                v00 = r0.x + gm*v00;  v01 = r0.y + gm*v01;
                v10 = r8.x + gm*v10;  v11 = r8.y + gm*v11;
                if (EPI == 1) {
                    s1 += v00+v01+v10+v11;
                    sq += v00*v00 + v01*v01 + v10*v10 + v11*v11;
                }
            }
            *(float2*)(out + i0) = make_float2(v00, v01);
            *(float2*)(out + i8) = make_float2(v10, v11);
        }
    }
    if (EPI == 1) {
        block_reduce2(s1, sq);
        if (tid == 0) { atomicAdd(&g_sums2[b*2], s1); atomicAdd(&g_sums2[b*2+1], sq); }
    }
}

// ---------- HMMA flash attention (unchanged from passing R7) ----------
__global__ void __launch_bounds__(128) attn_mma(
    const float* __restrict__ qkv, float* __restrict__ outp)
{
    extern __shared__ __nv_bfloat16 smb[];
    __nv_bfloat16* QH = smb;
    __nv_bfloat16* QL = QH + 64*ALD;
    __nv_bfloat16* KH = QL + 64*ALD;
    __nv_bfloat16* KL = KH + 64*ALD;
    __nv_bfloat16* VH = KL + 64*ALD;
    __nv_bfloat16* VL = VH + 64*ALD;

    int it = blockIdx.x, h = blockIdx.y, b = blockIdx.z;
    int tid = threadIdx.x, lane = tid & 31, w = tid >> 5;
    int g = lane >> 2, tq = lane & 3;
    int q0 = w * 16;

    const float* qb = qkv + ((size_t)b*3*CCH +          h*DKD) * NSP + it*64;
    const float* kb = qkv + ((size_t)b*3*CCH +   CCH +  h*DKD) * NSP;
    const float* vb = qkv + ((size_t)b*3*CCH + 2*CCH +  h*DKD) * NSP;

    const int lrow = lane & 7, lt = lane >> 3;
    const uint32_t a_off = (uint32_t)((q0 + ((lt & 1) << 3) + lrow) * (ALD*2) + (lt >> 1) * 16);
    const uint32_t b_off = (uint32_t)((((lt >> 1) << 3) + lrow) * (ALD*2) + (lt & 1) * 16);
    const uint32_t uQH = s2u(QH), uQL = s2u(QL);
    const uint32_t uKH = s2u(KH), uKL = s2u(KL);
    const uint32_t uVH = s2u(VH), uVL = s2u(VL);

    {
        int dp = tid >> 2, kg = tid & 3;
        const float* p0 = qb + (size_t)(2*dp) * NSP + kg*16;
        const float* p1 = p0 + NSP;
        #pragma unroll
        for (int qd = 0; qd < 4; qd++) {
            float4 fa = *(const float4*)(p0 + qd*4);
            float4 fb = *(const float4*)(p1 + qd*4);
            float va[4] = {fa.x, fa.y, fa.z, fa.w};
            float vbb[4] = {fb.x, fb.y, fb.z, fb.w};
            #pragma unroll
            for (int e = 0; e < 4; e++) {
                int qq = kg*16 + qd*4 + e;
                uint32_t H, L;
                pack2(va[e]*0.125f, vbb[e]*0.125f, H, L);
                *(uint32_t*)&QH[qq*ALD + 2*dp] = H;
                *(uint32_t*)&QL[qq*ALD + 2*dp] = L;
            }
        }
    }

    float m0 = -1e30f, m1 = -1e30f, l0 = 0.f, l1 = 0.f;
    float oacc[8][4] = {};

    for (int kt = 0; kt < 16; kt++) {
        __syncthreads();
        {
            int dp = tid >> 2, kg = tid & 3;
            const float* p0 = kb + (size_t)(2*dp) * NSP + kt*64 + kg*16;
            const float* p1 = p0 + NSP;
            #pragma unroll
            for (int qd = 0; qd < 4; qd++) {
                float4 fa = *(const float4*)(p0 + qd*4);
                float4 fb = *(const float4*)(p1 + qd*4);
                float va[4] = {fa.x, fa.y, fa.z, fa.w};
                float vbb[4] = {fb.x, fb.y, fb.z, fb.w};
                #pragma unroll
                for (int e = 0; e < 4; e++) {
                    int key = kg*16 + qd*4 + e;
                    uint32_t H, L;
                    pack2(va[e], vbb[e], H, L);
                    *(uint32_t*)&KH[key*ALD + 2*dp] = H;
                    *(uint32_t*)&KL[key*ALD + 2*dp] = L;
                }
            }
        }
        {
            int d = tid >> 1, j8 = (tid & 1) * 32;
            const float* p = vb + (size_t)d * NSP + kt*64 + j8;
            #pragma unroll
            for (int qd = 0; qd < 4; qd++) {
                float4 fa = *(const float4*)(p + qd*8);
                float4 fb = *(const float4*)(p + qd*8 + 4);
                float f[8] = {fa.x, fa.y, fa.z, fa.w, fb.x, fb.y, fb.z, fb.w};
                uint32_t H[4], L[4];
                #pragma unroll
                for (int e = 0; e < 4; e++) pack2(f[2*e], f[2*e+1], H[e], L[e]);
                *(uint4*)&VH[d*ALD + j8 + qd*8] = make_uint4(H[0], H[1], H[2], H[3]);
                *(uint4*)&VL[d*ALD + j8 + qd*8] = make_uint4(L[0], L[1], L[2], L[3]);
            }
        }
        __syncthreads();

        float sacc[8][4] = {};
        #pragma unroll
        for (int kc = 0; kc < 4; kc++) {
            uint32_t aH[4], aL[4];
            ldsm4(aH[0], aH[1], aH[2], aH[3], uQH + a_off + kc*32);
            ldsm4(aL[0], aL[1], aL[2], aL[3], uQL + a_off + kc*32);
            #pragma unroll
            for (int p = 0; p < 4; p++) {
                uint32_t h0, h1, h2, h3, x0, x1, x2, x3;
                ldsm4(h0, h1, h2, h3, uKH + b_off + p*16*(ALD*2) + kc*32);
                ldsm4(x0, x1, x2, x3, uKL + b_off + p*16*(ALD*2) + kc*32);
                MMA_B16(sacc[2*p  ], aH, h0, h1);
                MMA_B16(sacc[2*p  ], aH, x0, x1);
                MMA_B16(sacc[2*p  ], aL, h0, h1);
                MMA_B16(sacc[2*p+1], aH, h2, h3);
                MMA_B16(sacc[2*p+1], aH, x2, x3);
                MMA_B16(sacc[2*p+1], aL, h2, h3);
            }
        }

        float rm0 = -1e30f, rm1 = -1e30f;
        #pragma unroll
        for (int nf = 0; nf < 8; nf++) {
            rm0 = fmaxf(rm0, fmaxf(sacc[nf][0], sacc[nf][1]));
            rm1 = fmaxf(rm1, fmaxf(sacc[nf][2], sacc[nf][3]));
        }
        rm0 = fmaxf(rm0, __shfl_xor_sync(0xffffffffu, rm0, 1));
        rm0 = fmaxf(rm0, __shfl_xor_sync(0xffffffffu, rm0, 2));
        rm1 = fmaxf(rm1, __shfl_xor_sync(0xffffffffu, rm1, 1));
        rm1 = fmaxf(rm1, __shfl_xor_sync(0xffffffffu, rm1, 2));
        float mn0 = fmaxf(m0, rm0), mn1 = fmaxf(m1, rm1);
        float al0 = __expf(m0 - mn0), al1 = __expf(m1 - mn1);
        m0 = mn0; m1 = mn1;
        float ls0 = 0.f, ls1 = 0.f;
        #pragma unroll
        for (int nf = 0; nf < 8; nf++) {
            sacc[nf][0] = __expf(sacc[nf][0] - mn0);
            sacc[nf][1] = __expf(sacc[nf][1] - mn0);
            sacc[nf][2] = __expf(sacc[nf][2] - mn1);
            sacc[nf][3] = __expf(sacc[nf][3] - mn1);
            ls0 += sacc[nf][0] + sacc[nf][1];
            ls1 += sacc[nf][2] + sacc[nf][3];
        }
        ls0 += __shfl_xor_sync(0xffffffffu, ls0, 1);
        ls0 += __shfl_xor_sync(0xffffffffu, ls0, 2);
        ls1 += __shfl_xor_sync(0xffffffffu, ls1, 1);
        ls1 += __shfl_xor_sync(0xffffffffu, ls1, 2);
        l0 = l0 * al0 + ls0;
        l1 = l1 * al1 + ls1;
        #pragma unroll
        for (int nf = 0; nf < 8; nf++) {
            oacc[nf][0] *= al0; oacc[nf][1] *= al0;
            oacc[nf][2] *= al1; oacc[nf][3] *= al1;
        }

        uint32_t pH[4][4], pL[4][4];
        #pragma unroll
        for (int c = 0; c < 4; c++) {
            pack2(sacc[2*c  ][0], sacc[2*c  ][1], pH[c][0], pL[c][0]);
            pack2(sacc[2*c  ][2], sacc[2*c  ][3], pH[c][1], pL[c][1]);
            pack2(sacc[2*c+1][0], sacc[2*c+1][1], pH[c][2], pL[c][2]);
            pack2(sacc[2*c+1][2], sacc[2*c+1][3], pH[c][3], pL[c][3]);
        }

        #pragma unroll
        for (int c = 0; c < 4; c++) {
            #pragma unroll
            for (int p = 0; p < 4; p++) {
                uint32_t h0, h1, h2, h3, x0, x1, x2, x3;
                ldsm4(h0, h1, h2, h3, uVH + b_off + p*16*(ALD*2) + c*32);
                ldsm4(x0, x1, x2, x3, uVL + b_off + p*16*(ALD*2) + c*32);
                MMA_B16(oacc[2*p  ], pH[c], h0, h1);
                MMA_B16(oacc[2*p  ], pH[c], x0, x1);
                MMA_B16(oacc[2*p  ], pL[c], h0, h1);
                MMA_B16(oacc[2*p+1], pH[c], h2, h3);
                MMA_B16(oacc[2*p+1], pH[c], x2, x3);
                MMA_B16(oacc[2*p+1], pL[c], h2, h3);
            }
        }
    }

    __syncthreads();
    float inv0 = 1.f / l0, inv1 = 1.f / l1;
    float* OS = (float*)smb;
    #pragma unroll
    for (int nf = 0; nf < 8; nf++) {
        int d = nf*8 + 2*tq;
        OS[(d  )*64 + q0 + g    ] = oacc[nf][0] * inv0;
        OS[(d+1)*64 + q0 + g    ] = oacc[nf][1] * inv0;
        OS[(d  )*64 + q0 + g + 8] = oacc[nf][2] * inv1;
        OS[(d+1)*64 + q0 + g + 8] = oacc[nf][3] * inv1;
    }
    __syncthreads();
    {
        int d = tid >> 1, q8 = (tid & 1) * 32;
        float* ob = outp + ((size_t)b*CCH + h*DKD + d)*NSP + it*64 + q8;
        #pragma unroll
        for (int j = 0; j < 8; j++)
            *(float4*)(ob + j*4) = *(const float4*)&OS[d*64 + q8 + j*4];
    }
}

// ---------- launch ----------
#define ATTN_SMEM (6*64*ALD*2)
#define GEMM_SMEM (4*128*ALD*2)

extern "C" void kernel_launch(void* const* d_in, const int* in_sizes, int n_in,
                              void* d_out, int out_size) {
    const float* x     = (const float*)d_in[0];
    const float* qkv_w = (const float*)d_in[1];
    const float* uh_w  = (const float*)d_in[2];
    const float* uh_b  = (const float*)d_in[3];
    const float* n1_w  = (const float*)d_in[4];
    const float* n1_b  = (const float*)d_in[5];
    const float* n2_w  = (const float*)d_in[6];
    const float* n2_b  = (const float*)d_in[7];
    const float* f1_w  = (const float*)d_in[8];
    const float* f1_b  = (const float*)d_in[9];
    const float* f2_w  = (const float*)d_in[10];
    const float* f2_b  = (const float*)d_in[11];
    const float* g_at  = (const float*)d_in[12];
    const float* g_ff  = (const float*)d_in[13];
    float* out = (float*)d_out;

    float *qkv_buf, *attn_buf, *x2_buf, *h1_buf;
    cudaGetSymbolAddress((void**)&qkv_buf,  g_qkv);
    cudaGetSymbolAddress((void**)&attn_buf, g_attn);
    cudaGetSymbolAddress((void**)&x2_buf,   g_x2);
    cudaGetSymbolAddress((void**)&h1_buf,   g_h1);

    cudaFuncSetAttribute(attn_mma, cudaFuncAttributeMaxDynamicSharedMemorySize, ATTN_SMEM);
    cudaFuncSetAttribute(gemm_mma<256,1,0>,  cudaFuncAttributeMaxDynamicSharedMemorySize, GEMM_SMEM);
    cudaFuncSetAttribute(gemm_mma<256,0,1>,  cudaFuncAttributeMaxDynamicSharedMemorySize, GEMM_SMEM);
    cudaFuncSetAttribute(gemm_mma<256,2,2>,  cudaFuncAttributeMaxDynamicSharedMemorySize, GEMM_SMEM);
    cudaFuncSetAttribute(gemm_mma<1024,0,3>, cudaFuncAttributeMaxDynamicSharedMemorySize, GEMM_SMEM);

    zero_stats_kernel<<<1, 32>>>();
    gn_stats_kernel<<<dim3(32, BSZ), 256>>>(x);

    // qkv = qkv_w @ GN1(x)
    gemm_mma<256,1,0><<<dim3(8,6,BSZ), 256, GEMM_SMEM>>>(
        x, qkv_w, n1_w, n1_b, nullptr, nullptr, nullptr, qkv_buf);

    attn_mma<<<dim3(16, NHH, BSZ), 128, ATTN_SMEM>>>(qkv_buf, attn_buf);

    // x2 = x + g_at*(uh_w@attn + uh_b), + GN2 stats
    gemm_mma<256,0,1><<<dim3(8,2,BSZ), 256, GEMM_SMEM>>>(
        attn_buf, uh_w, nullptr, nullptr, uh_b, x, g_at, x2_buf);

    // h1 = silu(f1_w @ GN2(x2) + f1_b)
    gemm_mma<256,2,2><<<dim3(8,8,BSZ), 256, GEMM_SMEM>>>(
        x2_buf, f1_w, n2_w, n2_b, f1_b, nullptr, nullptr, h1_buf);

    // out = x2 + g_ff*(f2_w@h1 + f2_b)
    gemm_mma<1024,0,3><<<dim3(8,2,BSZ), 256, GEMM_SMEM>>>(
        h1_buf, f2_w, nullptr, nullptr, f2_b, x2_buf, g_ff, out);
}

// round 9
// speedup vs baseline: 1.9732x; 1.0810x over previous
#include <cuda_runtime.h>
#include <cuda_bf16.h>
#include <math.h>
#include <stdint.h>

#define BSZ 8
#define CCH 256
#define NSP 1024
#define NHH 4
#define DKD 64
#define CNT (CCH*NSP)

__device__ float g_sums1[2*BSZ];
__device__ float g_sums2[2*BSZ];
__device__ float g_qkv [(size_t)BSZ*3*CCH*NSP];
__device__ float g_attn[(size_t)BSZ*CCH*NSP];
__device__ float g_x2  [(size_t)BSZ*CCH*NSP];
__device__ float g_h1  [(size_t)BSZ*4*CCH*NSP];

// ---------- reductions / stats ----------
__device__ __forceinline__ void block_reduce2(float& s, float& s2) {
    #pragma unroll
    for (int o = 16; o; o >>= 1) {
        s  += __shfl_xor_sync(0xffffffffu, s,  o);
        s2 += __shfl_xor_sync(0xffffffffu, s2, o);
    }
    __shared__ float sh0[8], sh1[8];
    int w = threadIdx.x >> 5, l = threadIdx.x & 31;
    if (l == 0) { sh0[w] = s; sh1[w] = s2; }
    __syncthreads();
    if (w == 0) {
        s  = (l < 8) ? sh0[l] : 0.f;
        s2 = (l < 8) ? sh1[l] : 0.f;
        #pragma unroll
        for (int o = 4; o; o >>= 1) {
            s  += __shfl_xor_sync(0xffffffffu, s,  o);
            s2 += __shfl_xor_sync(0xffffffffu, s2, o);
        }
    }
}

__global__ void zero_stats_kernel() {
    int t = threadIdx.x;
    if (t < 2*BSZ) { g_sums1[t] = 0.f; g_sums2[t] = 0.f; }
}

__global__ void gn_stats_kernel(const float* __restrict__ x) {
    int b = blockIdx.y;
    const float* xb = x + (size_t)b * CNT;
    int base = blockIdx.x * (CNT / 32);
    float s = 0.f, s2 = 0.f;
    for (int i = threadIdx.x; i < CNT/32; i += 256) {
        float v = xb[base + i];
        s += v; s2 += v*v;
    }
    block_reduce2(s, s2);
    if (threadIdx.x == 0) {
        atomicAdd(&g_sums1[b*2],   s);
        atomicAdd(&g_sums1[b*2+1], s2);
    }
}

// ---------- HMMA helpers ----------
#define MMA_B16(c, a, b0, b1) \
  asm volatile("mma.sync.aligned.m16n8k16.row.col.f32.bf16.bf16.f32 " \
    "{%0,%1,%2,%3}, {%4,%5,%6,%7}, {%8,%9}, {%0,%1,%2,%3};" \
    : "+f"((c)[0]),"+f"((c)[1]),"+f"((c)[2]),"+f"((c)[3]) \
    : "r"((a)[0]),"r"((a)[1]),"r"((a)[2]),"r"((a)[3]), "r"(b0),"r"(b1))

__device__ __forceinline__ void ldsm4(uint32_t& r0, uint32_t& r1, uint32_t& r2,
                                      uint32_t& r3, uint32_t addr) {
    asm volatile("ldmatrix.sync.aligned.m8n8.x4.shared.b16 {%0,%1,%2,%3}, [%4];"
        : "=r"(r0), "=r"(r1), "=r"(r2), "=r"(r3) : "r"(addr));
}
__device__ __forceinline__ uint32_t s2u(const void* p) {
    return (uint32_t)__cvta_generic_to_shared(p);
}
__device__ __forceinline__ void pack2(float a, float b, uint32_t& h, uint32_t& l) {
    __nv_bfloat162 hb = __floats2bfloat162_rn(a, b);
    float ra = a - __bfloat162float(hb.x);
    float rb = b - __bfloat162float(hb.y);
    __nv_bfloat162 lb = __floats2bfloat162_rn(ra, rb);
    h = *(uint32_t*)&hb; l = *(uint32_t*)&lb;
}

#define ALD 72   // bf16 row stride: 144 B rows, 16B-aligned, conflict-free ldmatrix

// ---------- fused HMMA GEMM (unchanged from passing R8) ----------
template<int K, int NORMSRC, int EPI>
__global__ void __launch_bounds__(256) gemm_mma(
    const float* __restrict__ Act, const float* __restrict__ W,
    const float* __restrict__ gw, const float* __restrict__ gb,
    const float* __restrict__ bias, const float* __restrict__ resid,
    const float* __restrict__ gamma, float* __restrict__ out)
{
    constexpr int MT = (EPI==0)?768:(EPI==2)?1024:256;
    extern __shared__ __nv_bfloat16 smg[];
    __nv_bfloat16* AsH = smg;
    __nv_bfloat16* AsL = AsH + 128*ALD;
    __nv_bfloat16* BsH = AsL + 128*ALD;
    __nv_bfloat16* BsL = BsH + 128*ALD;

    int tid = threadIdx.x, lane = tid & 31, w = tid >> 5;
    int wm = w & 3, wn = w >> 2;
    int t0 = blockIdx.x * 128, m0 = blockIdx.y * 128, b = blockIdx.z;

    float mean = 0.f, rstd = 0.f;
    if (NORMSRC) {
        const float* s = (NORMSRC == 1) ? g_sums1 : g_sums2;
        mean = s[b*2] * (1.f/CNT);
        rstd = rsqrtf(s[b*2+1] * (1.f/CNT) - mean*mean + 1e-5f);
    }

    float acc[2][8][4] = {};
    const int g = lane >> 2, tq = lane & 3;
    const int lrow = lane & 7, lt = lane >> 3;
    const uint32_t a_off = (uint32_t)((wm*32 + ((lt & 1) << 3) + lrow) * (ALD*2) + (lt >> 1) * 16);
    const uint32_t b_off = (uint32_t)(((wn*64) + ((lt >> 1) << 3) + lrow) * (ALD*2) + (lt & 1) * 16);
    const uint32_t uAH = s2u(AsH), uAL = s2u(AsL);
    const uint32_t uBH = s2u(BsH), uBL = s2u(BsL);

    const int sm_m = tid >> 1, sm_kh = (tid & 1) * 32;
    const int sdp = tid & 31, stg = tid >> 5;

    for (int c = 0; c < K/64; c++) {
        int kc = c * 64;
        {
            const float* p = W + (size_t)(m0 + sm_m)*K + kc + sm_kh;
            #pragma unroll
            for (int qd = 0; qd < 4; qd++) {
                float4 fa = *(const float4*)(p + qd*8);
                float4 fb = *(const float4*)(p + qd*8 + 4);
                float f[8] = {fa.x, fa.y, fa.z, fa.w, fb.x, fb.y, fb.z, fb.w};
                uint32_t H[4], L[4];
                #pragma unroll
                for (int e = 0; e < 4; e++) pack2(f[2*e], f[2*e+1], H[e], L[e]);
                *(uint4*)&AsH[sm_m*ALD + sm_kh + qd*8] = make_uint4(H[0], H[1], H[2], H[3]);
                *(uint4*)&AsL[sm_m*ALD + sm_kh + qd*8] = make_uint4(L[0], L[1], L[2], L[3]);
            }
        }
        {
            int ch = kc + 2*sdp;
            float gw0 = 1.f, gb0 = 0.f, gw1 = 1.f, gb1 = 0.f;
            if (NORMSRC) { gw0 = gw[ch]*rstd; gb0 = gb[ch] - mean*gw0;
                           gw1 = gw[ch+1]*rstd; gb1 = gb[ch+1] - mean*gw1; }
            const float* p0 = Act + ((size_t)b*K + ch)*NSP + t0 + stg*16;
            const float* p1 = p0 + NSP;
            #pragma unroll
            for (int qd = 0; qd < 4; qd++) {
                float4 fa = *(const float4*)(p0 + qd*4);
                float4 fb = *(const float4*)(p1 + qd*4);
                float va[4] = {fa.x, fa.y, fa.z, fa.w};
                float vbb[4] = {fb.x, fb.y, fb.z, fb.w};
                #pragma unroll
                for (int e = 0; e < 4; e++) {
                    float v0 = NORMSRC ? va[e]*gw0 + gb0 : va[e];
                    float v1 = NORMSRC ? vbb[e]*gw1 + gb1 : vbb[e];
                    int tok = stg*16 + qd*4 + e;
                    uint32_t H, L;
                    pack2(v0, v1, H, L);
                    *(uint32_t*)&BsH[tok*ALD + 2*sdp] = H;
                    *(uint32_t*)&BsL[tok*ALD + 2*sdp] = L;
                }
            }
        }
        __syncthreads();

        #pragma unroll
        for (int k4 = 0; k4 < 4; k4++) {
            uint32_t aH[2][4], aL[2][4];
            #pragma unroll
            for (int mf = 0; mf < 2; mf++) {
                ldsm4(aH[mf][0], aH[mf][1], aH[mf][2], aH[mf][3],
                      uAH + a_off + mf*16*(ALD*2) + k4*32);
                ldsm4(aL[mf][0], aL[mf][1], aL[mf][2], aL[mf][3],
                      uAL + a_off + mf*16*(ALD*2) + k4*32);
            }
            #pragma unroll
            for (int p = 0; p < 4; p++) {
                uint32_t h0, h1, h2, h3, x0, x1, x2, x3;
                ldsm4(h0, h1, h2, h3, uBH + b_off + p*16*(ALD*2) + k4*32);
                ldsm4(x0, x1, x2, x3, uBL + b_off + p*16*(ALD*2) + k4*32);
                #pragma unroll
                for (int mf = 0; mf < 2; mf++) {
                    MMA_B16(acc[mf][2*p  ], aH[mf], h0, h1);
                    MMA_B16(acc[mf][2*p  ], aH[mf], x0, x1);
                    MMA_B16(acc[mf][2*p  ], aL[mf], h0, h1);
                    MMA_B16(acc[mf][2*p+1], aH[mf], h2, h3);
                    MMA_B16(acc[mf][2*p+1], aH[mf], x2, x3);
                    MMA_B16(acc[mf][2*p+1], aL[mf], h2, h3);
                }
            }
        }
        __syncthreads();
    }

    float gm = (EPI==1 || EPI==3) ? gamma[0] : 0.f;
    float s1 = 0.f, sq = 0.f;
    #pragma unroll
    for (int mf = 0; mf < 2; mf++) {
        int row = m0 + wm*32 + mf*16 + g;
        float bi0 = (EPI!=0) ? bias[row]     : 0.f;
        float bi8 = (EPI!=0) ? bias[row + 8] : 0.f;
        #pragma unroll
        for (int nf = 0; nf < 8; nf++) {
            int col = t0 + wn*64 + nf*8 + tq*2;
            float v00 = acc[mf][nf][0] + bi0;
            float v01 = acc[mf][nf][1] + bi0;
            float v10 = acc[mf][nf][2] + bi8;
            float v11 = acc[mf][nf][3] + bi8;
            size_t i0 = ((size_t)b*MT + row    )*NSP + col;
            size_t i8 = ((size_t)b*MT + row + 8)*NSP + col;
            if (EPI == 2) {
                v00 = v00 / (1.f + __expf(-v00));
                v01 = v01 / (1.f + __expf(-v01));
                v10 = v10 / (1.f + __expf(-v10));
                v11 = v11 / (1.f + __expf(-v11));
            } else if (EPI == 1 || EPI == 3) {
                float2 r0 = *(const float2*)(resid + i0);
                float2 r8 = *(const float2*)(resid + i8);
                v00 = r0.x + gm*v00;  v01 = r0.y + gm*v01;
                v10 = r8.x + gm*v10;  v11 = r8.y + gm*v11;
                if (EPI == 1) {
                    s1 += v00+v01+v10+v11;
                    sq += v00*v00 + v01*v01 + v10*v10 + v11*v11;
                }
            }
            *(float2*)(out + i0) = make_float2(v00, v01);
            *(float2*)(out + i8) = make_float2(v10, v11);
        }
    }
    if (EPI == 1) {
        block_reduce2(s1, sq);
        if (tid == 0) { atomicAdd(&g_sums2[b*2], s1); atomicAdd(&g_sums2[b*2+1], sq); }
    }
}

// ---------- HMMA flash attention: 8 warps, 128 queries per CTA ----------
__global__ void __launch_bounds__(256) attn_mma(
    const float* __restrict__ qkv, float* __restrict__ outp)
{
    extern __shared__ __nv_bfloat16 smb[];
    __nv_bfloat16* QH = smb;                  // [128][ALD]
    __nv_bfloat16* QL = QH + 128*ALD;
    __nv_bfloat16* KH = QL + 128*ALD;         // [64][ALD]
    __nv_bfloat16* KL = KH + 64*ALD;
    __nv_bfloat16* VH = KL + 64*ALD;
    __nv_bfloat16* VL = VH + 64*ALD;

    int it = blockIdx.x, h = blockIdx.y, b = blockIdx.z;
    int tid = threadIdx.x, lane = tid & 31, w = tid >> 5;
    int g = lane >> 2, tq = lane & 3;
    int q0 = w * 16;                          // warp's queries within 128-row block

    const float* qb = qkv + ((size_t)b*3*CCH +          h*DKD) * NSP + it*128;
    const float* kb = qkv + ((size_t)b*3*CCH +   CCH +  h*DKD) * NSP;
    const float* vb = qkv + ((size_t)b*3*CCH + 2*CCH +  h*DKD) * NSP;

    const int lrow = lane & 7, lt = lane >> 3;
    const uint32_t a_off = (uint32_t)((q0 + ((lt & 1) << 3) + lrow) * (ALD*2) + (lt >> 1) * 16);
    const uint32_t b_off = (uint32_t)((((lt >> 1) << 3) + lrow) * (ALD*2) + (lt & 1) * 16);
    const uint32_t uQH = s2u(QH), uQL = s2u(QL);
    const uint32_t uKH = s2u(KH), uKL = s2u(KL);
    const uint32_t uVH = s2u(VH), uVL = s2u(VL);

    // stage Q (128 rows): thread owns d-pair 2dp x 16 queries
    {
        int dp = tid & 31, qg = tid >> 5;
        const float* p0 = qb + (size_t)(2*dp) * NSP + qg*16;
        const float* p1 = p0 + NSP;
        #pragma unroll
        for (int qd = 0; qd < 4; qd++) {
            float4 fa = *(const float4*)(p0 + qd*4);
            float4 fb = *(const float4*)(p1 + qd*4);
            float va[4] = {fa.x, fa.y, fa.z, fa.w};
            float vbb[4] = {fb.x, fb.y, fb.z, fb.w};
            #pragma unroll
            for (int e = 0; e < 4; e++) {
                int qq = qg*16 + qd*4 + e;
                uint32_t H, L;
                pack2(va[e]*0.125f, vbb[e]*0.125f, H, L);
                *(uint32_t*)&QH[qq*ALD + 2*dp] = H;
                *(uint32_t*)&QL[qq*ALD + 2*dp] = L;
            }
        }
    }

    float m0 = -1e30f, m1 = -1e30f, l0 = 0.f, l1 = 0.f;
    float oacc[8][4] = {};

    for (int kt = 0; kt < 16; kt++) {
        __syncthreads();
        // stage K (64 keys): thread owns d-pair 2dp x 8 keys
        {
            int dp = tid & 31, kg = tid >> 5;
            const float* p0 = kb + (size_t)(2*dp) * NSP + kt*64 + kg*8;
            const float* p1 = p0 + NSP;
            #pragma unroll
            for (int qd = 0; qd < 2; qd++) {
                float4 fa = *(const float4*)(p0 + qd*4);
                float4 fb = *(const float4*)(p1 + qd*4);
                float va[4] = {fa.x, fa.y, fa.z, fa.w};
                float vbb[4] = {fb.x, fb.y, fb.z, fb.w};
                #pragma unroll
                for (int e = 0; e < 4; e++) {
                    int key = kg*8 + qd*4 + e;
                    uint32_t H, L;
                    pack2(va[e], vbb[e], H, L);
                    *(uint32_t*)&KH[key*ALD + 2*dp] = H;
                    *(uint32_t*)&KL[key*ALD + 2*dp] = L;
                }
            }
        }
        // stage V [d][j]: thread owns d x 16 j; STS.128
        {
            int d = tid & 63, j16 = (tid >> 6) * 16;
            const float* p = vb + (size_t)d * NSP + kt*64 + j16;
            #pragma unroll
            for (int qd = 0; qd < 2; qd++) {
                float4 fa = *(const float4*)(p + qd*8);
                float4 fb = *(const float4*)(p + qd*8 + 4);
                float f[8] = {fa.x, fa.y, fa.z, fa.w, fb.x, fb.y, fb.z, fb.w};
                uint32_t H[4], L[4];
                #pragma unroll
                for (int e = 0; e < 4; e++) pack2(f[2*e], f[2*e+1], H[e], L[e]);
                *(uint4*)&VH[d*ALD + j16 + qd*8] = make_uint4(H[0], H[1], H[2], H[3]);
                *(uint4*)&VL[d*ALD + j16 + qd*8] = make_uint4(L[0], L[1], L[2], L[3]);
            }
        }
        __syncthreads();

        // S = Q K^T (16 x 64 per warp), split-bf16 3-MMA
        float sacc[8][4] = {};
        #pragma unroll
        for (int kc = 0; kc < 4; kc++) {
            uint32_t aH[4], aL[4];
            ldsm4(aH[0], aH[1], aH[2], aH[3], uQH + a_off + kc*32);
            ldsm4(aL[0], aL[1], aL[2], aL[3], uQL + a_off + kc*32);
            #pragma unroll
            for (int p = 0; p < 4; p++) {
                uint32_t h0, h1, h2, h3, x0, x1, x2, x3;
                ldsm4(h0, h1, h2, h3, uKH + b_off + p*16*(ALD*2) + kc*32);
                ldsm4(x0, x1, x2, x3, uKL + b_off + p*16*(ALD*2) + kc*32);
                MMA_B16(sacc[2*p  ], aH, h0, h1);
                MMA_B16(sacc[2*p  ], aH, x0, x1);
                MMA_B16(sacc[2*p  ], aL, h0, h1);
                MMA_B16(sacc[2*p+1], aH, h2, h3);
                MMA_B16(sacc[2*p+1], aH, x2, x3);
                MMA_B16(sacc[2*p+1], aL, h2, h3);
            }
        }

        // online softmax (rows q0+g and q0+g+8)
        float rm0 = -1e30f, rm1 = -1e30f;
        #pragma unroll
        for (int nf = 0; nf < 8; nf++) {
            rm0 = fmaxf(rm0, fmaxf(sacc[nf][0], sacc[nf][1]));
            rm1 = fmaxf(rm1, fmaxf(sacc[nf][2], sacc[nf][3]));
        }
        rm0 = fmaxf(rm0, __shfl_xor_sync(0xffffffffu, rm0, 1));
        rm0 = fmaxf(rm0, __shfl_xor_sync(0xffffffffu, rm0, 2));
        rm1 = fmaxf(rm1, __shfl_xor_sync(0xffffffffu, rm1, 1));
        rm1 = fmaxf(rm1, __shfl_xor_sync(0xffffffffu, rm1, 2));
        float mn0 = fmaxf(m0, rm0), mn1 = fmaxf(m1, rm1);
        float al0 = __expf(m0 - mn0), al1 = __expf(m1 - mn1);
        m0 = mn0; m1 = mn1;
        float ls0 = 0.f, ls1 = 0.f;
        #pragma unroll
        for (int nf = 0; nf < 8; nf++) {
            sacc[nf][0] = __expf(sacc[nf][0] - mn0);
            sacc[nf][1] = __expf(sacc[nf][1] - mn0);
            sacc[nf][2] = __expf(sacc[nf][2] - mn1);
            sacc[nf][3] = __expf(sacc[nf][3] - mn1);
            ls0 += sacc[nf][0] + sacc[nf][1];
            ls1 += sacc[nf][2] + sacc[nf][3];
        }
        ls0 += __shfl_xor_sync(0xffffffffu, ls0, 1);
        ls0 += __shfl_xor_sync(0xffffffffu, ls0, 2);
        ls1 += __shfl_xor_sync(0xffffffffu, ls1, 1);
        ls1 += __shfl_xor_sync(0xffffffffu, ls1, 2);
        l0 = l0 * al0 + ls0;
        l1 = l1 * al1 + ls1;
        #pragma unroll
        for (int nf = 0; nf < 8; nf++) {
            oacc[nf][0] *= al0; oacc[nf][1] *= al0;
            oacc[nf][2] *= al1; oacc[nf][3] *= al1;
        }

        // P fragments in registers
        uint32_t pH[4][4], pL[4][4];
        #pragma unroll
        for (int c = 0; c < 4; c++) {
            pack2(sacc[2*c  ][0], sacc[2*c  ][1], pH[c][0], pL[c][0]);
            pack2(sacc[2*c  ][2], sacc[2*c  ][3], pH[c][1], pL[c][1]);
            pack2(sacc[2*c+1][0], sacc[2*c+1][1], pH[c][2], pL[c][2]);
            pack2(sacc[2*c+1][2], sacc[2*c+1][3], pH[c][3], pL[c][3]);
        }

        // O += P V
        #pragma unroll
        for (int c = 0; c < 4; c++) {
            #pragma unroll
            for (int p = 0; p < 4; p++) {
                uint32_t h0, h1, h2, h3, x0, x1, x2, x3;
                ldsm4(h0, h1, h2, h3, uVH + b_off + p*16*(ALD*2) + c*32);
                ldsm4(x0, x1, x2, x3, uVL + b_off + p*16*(ALD*2) + c*32);
                MMA_B16(oacc[2*p  ], pH[c], h0, h1);
                MMA_B16(oacc[2*p  ], pH[c], x0, x1);
                MMA_B16(oacc[2*p  ], pL[c], h0, h1);
                MMA_B16(oacc[2*p+1], pH[c], h2, h3);
                MMA_B16(oacc[2*p+1], pH[c], x2, x3);
                MMA_B16(oacc[2*p+1], pL[c], h2, h3);
            }
        }
    }

    // finalize: transpose via smem (overlay Q region), coalesced writes
    __syncthreads();
    float inv0 = 1.f / l0, inv1 = 1.f / l1;
    float* OS = (float*)smb;   // [64 d][128 q]; 32 KB <= Q region 36.8 KB
    #pragma unroll
    for (int nf = 0; nf < 8; nf++) {
        int d = nf*8 + 2*tq;
        OS[(d  )*128 + q0 + g    ] = oacc[nf][0] * inv0;
        OS[(d+1)*128 + q0 + g    ] = oacc[nf][1] * inv0;
        OS[(d  )*128 + q0 + g + 8] = oacc[nf][2] * inv1;
        OS[(d+1)*128 + q0 + g + 8] = oacc[nf][3] * inv1;
    }
    __syncthreads();
    {
        int d = tid >> 2, q32 = (tid & 3) * 32;
        float* ob = outp + ((size_t)b*CCH + h*DKD + d)*NSP + it*128 + q32;
        #pragma unroll
        for (int j = 0; j < 8; j++)
            *(float4*)(ob + j*4) = *(const float4*)&OS[d*128 + q32 + j*4];
    }
}

// ---------- launch ----------
#define ATTN_SMEM ((2*128 + 4*64)*ALD*2)
#define GEMM_SMEM (4*128*ALD*2)

extern "C" void kernel_launch(void* const* d_in, const int* in_sizes, int n_in,
                              void* d_out, int out_size) {
    const float* x     = (const float*)d_in[0];
    const float* qkv_w = (const float*)d_in[1];
    const float* uh_w  = (const float*)d_in[2];
    const float* uh_b  = (const float*)d_in[3];
    const float* n1_w  = (const float*)d_in[4];
    const float* n1_b  = (const float*)d_in[5];
    const float* n2_w  = (const float*)d_in[6];
    const float* n2_b  = (const float*)d_in[7];
    const float* f1_w  = (const float*)d_in[8];
    const float* f1_b  = (const float*)d_in[9];
    const float* f2_w  = (const float*)d_in[10];
    const float* f2_b  = (const float*)d_in[11];
    const float* g_at  = (const float*)d_in[12];
    const float* g_ff  = (const float*)d_in[13];
    float* out = (float*)d_out;

    float *qkv_buf, *attn_buf, *x2_buf, *h1_buf;
    cudaGetSymbolAddress((void**)&qkv_buf,  g_qkv);
    cudaGetSymbolAddress((void**)&attn_buf, g_attn);
    cudaGetSymbolAddress((void**)&x2_buf,   g_x2);
    cudaGetSymbolAddress((void**)&h1_buf,   g_h1);

    cudaFuncSetAttribute(attn_mma, cudaFuncAttributeMaxDynamicSharedMemorySize, ATTN_SMEM);
    cudaFuncSetAttribute(gemm_mma<256,1,0>,  cudaFuncAttributeMaxDynamicSharedMemorySize, GEMM_SMEM);
    cudaFuncSetAttribute(gemm_mma<256,0,1>,  cudaFuncAttributeMaxDynamicSharedMemorySize, GEMM_SMEM);
    cudaFuncSetAttribute(gemm_mma<256,2,2>,  cudaFuncAttributeMaxDynamicSharedMemorySize, GEMM_SMEM);
    cudaFuncSetAttribute(gemm_mma<1024,0,3>, cudaFuncAttributeMaxDynamicSharedMemorySize, GEMM_SMEM);

    zero_stats_kernel<<<1, 32>>>();
    gn_stats_kernel<<<dim3(32, BSZ), 256>>>(x);

    // qkv = qkv_w @ GN1(x)
    gemm_mma<256,1,0><<<dim3(8,6,BSZ), 256, GEMM_SMEM>>>(
        x, qkv_w, n1_w, n1_b, nullptr, nullptr, nullptr, qkv_buf);

    attn_mma<<<dim3(8, NHH, BSZ), 256, ATTN_SMEM>>>(qkv_buf, attn_buf);

    // x2 = x + g_at*(uh_w@attn + uh_b), + GN2 stats
    gemm_mma<256,0,1><<<dim3(8,2,BSZ), 256, GEMM_SMEM>>>(
        attn_buf, uh_w, nullptr, nullptr, uh_b, x, g_at, x2_buf);

    // h1 = silu(f1_w @ GN2(x2) + f1_b)
    gemm_mma<256,2,2><<<dim3(8,8,BSZ), 256, GEMM_SMEM>>>(
        x2_buf, f1_w, n2_w, n2_b, f1_b, nullptr, nullptr, h1_buf);

    // out = x2 + g_ff*(f2_w@h1 + f2_b)
    gemm_mma<1024,0,3><<<dim3(8,2,BSZ), 256, GEMM_SMEM>>>(
        h1_buf, f2_w, nullptr, nullptr, f2_b, x2_buf, g_ff, out);
}

// round 11
// speedup vs baseline: 2.2405x; 1.1354x over previous
#include <cuda_runtime.h>
#include <cuda_bf16.h>
#include <math.h>
#include <stdint.h>

#define BSZ 8
#define CCH 256
#define NSP 1024
#define NHH 4
#define DKD 64
#define CNT (CCH*NSP)

__device__ float g_sums1[2*BSZ];
__device__ float g_sums2[2*BSZ];
__device__ float g_qkv [(size_t)BSZ*3*CCH*NSP];
__device__ float g_attn[(size_t)BSZ*CCH*NSP];
__device__ float g_x2  [(size_t)BSZ*CCH*NSP];
__device__ float g_h1  [(size_t)BSZ*4*CCH*NSP];

// preconverted split-bf16 weights: [qkv 196608][uh 65536][f1 262144][f2 262144]
#define W_QKV 0
#define W_UH  196608
#define W_F1  262144
#define W_F2  524288
__device__ __nv_bfloat16 g_wH[786432];
__device__ __nv_bfloat16 g_wL[786432];

// ---------- reductions / stats ----------
__device__ __forceinline__ void block_reduce2(float& s, float& s2) {
    #pragma unroll
    for (int o = 16; o; o >>= 1) {
        s  += __shfl_xor_sync(0xffffffffu, s,  o);
        s2 += __shfl_xor_sync(0xffffffffu, s2, o);
    }
    __shared__ float sh0[8], sh1[8];
    int w = threadIdx.x >> 5, l = threadIdx.x & 31;
    if (l == 0) { sh0[w] = s; sh1[w] = s2; }
    __syncthreads();
    if (w == 0) {
        s  = (l < 8) ? sh0[l] : 0.f;
        s2 = (l < 8) ? sh1[l] : 0.f;
        #pragma unroll
        for (int o = 4; o; o >>= 1) {
            s  += __shfl_xor_sync(0xffffffffu, s,  o);
            s2 += __shfl_xor_sync(0xffffffffu, s2, o);
        }
    }
}

__global__ void zero_stats_kernel() {
    int t = threadIdx.x;
    if (t < 2*BSZ) { g_sums1[t] = 0.f; g_sums2[t] = 0.f; }
}

__global__ void gn_stats_kernel(const float* __restrict__ x) {
    int b = blockIdx.y;
    const float* xb = x + (size_t)b * CNT;
    int base = blockIdx.x * (CNT / 32);
    float s = 0.f, s2 = 0.f;
    for (int i = threadIdx.x; i < CNT/32; i += 256) {
        float v = xb[base + i];
        s += v; s2 += v*v;
    }
    block_reduce2(s, s2);
    if (threadIdx.x == 0) {
        atomicAdd(&g_sums1[b*2],   s);
        atomicAdd(&g_sums1[b*2+1], s2);
    }
}

// ---------- HMMA helpers ----------
#define MMA_B16(c, a, b0, b1) \
  asm volatile("mma.sync.aligned.m16n8k16.row.col.f32.bf16.bf16.f32 " \
    "{%0,%1,%2,%3}, {%4,%5,%6,%7}, {%8,%9}, {%0,%1,%2,%3};" \
    : "+f"((c)[0]),"+f"((c)[1]),"+f"((c)[2]),"+f"((c)[3]) \
    : "r"((a)[0]),"r"((a)[1]),"r"((a)[2]),"r"((a)[3]), "r"(b0),"r"(b1))

__device__ __forceinline__ void ldsm4(uint32_t& r0, uint32_t& r1, uint32_t& r2,
                                      uint32_t& r3, uint32_t addr) {
    asm volatile("ldmatrix.sync.aligned.m8n8.x4.shared.b16 {%0,%1,%2,%3}, [%4];"
        : "=r"(r0), "=r"(r1), "=r"(r2), "=r"(r3) : "r"(addr));
}
__device__ __forceinline__ uint32_t s2u(const void* p) {
    return (uint32_t)__cvta_generic_to_shared(p);
}
__device__ __forceinline__ void pack2(float a, float b, uint32_t& h, uint32_t& l) {
    __nv_bfloat162 hb = __floats2bfloat162_rn(a, b);
    float ra = a - __bfloat162float(hb.x);
    float rb = b - __bfloat162float(hb.y);
    __nv_bfloat162 lb = __floats2bfloat162_rn(ra, rb);
    h = *(uint32_t*)&hb; l = *(uint32_t*)&lb;
}

// one-shot weight split: 2 elems/thread
__global__ void convert_w_kernel(const float* __restrict__ src,
                                 __nv_bfloat16* __restrict__ dH,
                                 __nv_bfloat16* __restrict__ dL, int n2) {
    int i = blockIdx.x * blockDim.x + threadIdx.x;
    if (i < n2) {
        float2 f = *(const float2*)(src + 2*i);
        uint32_t H, L;
        pack2(f.x, f.y, H, L);
        *(uint32_t*)(dH + 2*i) = H;
        *(uint32_t*)(dL + 2*i) = L;
    }
}

#define ALD 72   // bf16 row stride: 144 B rows, 16B-aligned, conflict-free ldmatrix

// ---------- fused HMMA GEMM: preconverted weights via cp.async ----------
template<int K, int NORMSRC, int EPI>
__global__ void __launch_bounds__(256) gemm_mma(
    const float* __restrict__ Act,
    const __nv_bfloat16* __restrict__ WH, const __nv_bfloat16* __restrict__ WL,
    const float* __restrict__ gw, const float* __restrict__ gb,
    const float* __restrict__ bias, const float* __restrict__ resid,
    const float* __restrict__ gamma, float* __restrict__ out)
{
    constexpr int MT = (EPI==0)?768:(EPI==2)?1024:256;
    extern __shared__ __nv_bfloat16 smg[];
    __nv_bfloat16* AsH = smg;
    __nv_bfloat16* AsL = AsH + 128*ALD;
    __nv_bfloat16* BsH = AsL + 128*ALD;
    __nv_bfloat16* BsL = BsH + 128*ALD;

    int tid = threadIdx.x, lane = tid & 31, w = tid >> 5;
    int wm = w & 3, wn = w >> 2;
    int t0 = blockIdx.x * 128, m0 = blockIdx.y * 128, b = blockIdx.z;

    float mean = 0.f, rstd = 0.f;
    if (NORMSRC) {
        const float* s = (NORMSRC == 1) ? g_sums1 : g_sums2;
        mean = s[b*2] * (1.f/CNT);
        rstd = rsqrtf(s[b*2+1] * (1.f/CNT) - mean*mean + 1e-5f);
    }

    float acc[2][8][4] = {};
    const int g = lane >> 2, tq = lane & 3;
    const int lrow = lane & 7, lt = lane >> 3;
    const uint32_t a_off = (uint32_t)((wm*32 + ((lt & 1) << 3) + lrow) * (ALD*2) + (lt >> 1) * 16);
    const uint32_t b_off = (uint32_t)(((wn*64) + ((lt >> 1) << 3) + lrow) * (ALD*2) + (lt & 1) * 16);
    const uint32_t uAH = s2u(AsH), uAL = s2u(AsL);
    const uint32_t uBH = s2u(BsH), uBL = s2u(BsL);

    const int sm_m = tid >> 1, sm_kh = (tid & 1) * 32;
    const int sdp = tid & 31, stg = tid >> 5;

    for (int c = 0; c < K/64; c++) {
        int kc = c * 64;
        // ---- weights: cp.async preconverted bf16 (32 bf16 = 64B per buffer) ----
        {
            const __nv_bfloat16* pH = WH + (size_t)(m0 + sm_m)*K + kc + sm_kh;
            const __nv_bfloat16* pL = WL + (size_t)(m0 + sm_m)*K + kc + sm_kh;
            uint32_t dH = uAH + (uint32_t)(sm_m*ALD + sm_kh)*2;
            uint32_t dL = uAL + (uint32_t)(sm_m*ALD + sm_kh)*2;
            asm volatile(
                "cp.async.cg.shared.global [%0], [%1], 16;\n\t"
                "cp.async.cg.shared.global [%2], [%3], 16;\n\t"
                "cp.async.cg.shared.global [%4], [%5], 16;\n\t"
                "cp.async.cg.shared.global [%6], [%7], 16;\n\t"
                :: "r"(dH),    "l"(pH),    "r"(dH+16), "l"(pH+8),
                   "r"(dH+32), "l"(pH+16), "r"(dH+48), "l"(pH+24) : "memory");
            asm volatile(
                "cp.async.cg.shared.global [%0], [%1], 16;\n\t"
                "cp.async.cg.shared.global [%2], [%3], 16;\n\t"
                "cp.async.cg.shared.global [%4], [%5], 16;\n\t"
                "cp.async.cg.shared.global [%6], [%7], 16;\n\t"
                "cp.async.commit_group;\n\t"
                :: "r"(dL),    "l"(pL),    "r"(dL+16), "l"(pL+8),
                   "r"(dL+32), "l"(pL+16), "r"(dL+48), "l"(pL+24) : "memory");
        }
        // ---- activations: transpose, GN fused, packed STS.32 ----
        {
            int ch = kc + 2*sdp;
            float gw0 = 1.f, gb0 = 0.f, gw1 = 1.f, gb1 = 0.f;
            if (NORMSRC) { gw0 = gw[ch]*rstd; gb0 = gb[ch] - mean*gw0;
                           gw1 = gw[ch+1]*rstd; gb1 = gb[ch+1] - mean*gw1; }
            const float* p0 = Act + ((size_t)b*K + ch)*NSP + t0 + stg*16;
            const float* p1 = p0 + NSP;
            #pragma unroll
            for (int qd = 0; qd < 4; qd++) {
                float4 fa = *(const float4*)(p0 + qd*4);
                float4 fb = *(const float4*)(p1 + qd*4);
                float va[4] = {fa.x, fa.y, fa.z, fa.w};
                float vbb[4] = {fb.x, fb.y, fb.z, fb.w};
                #pragma unroll
                for (int e = 0; e < 4; e++) {
                    float v0 = NORMSRC ? va[e]*gw0 + gb0 : va[e];
                    float v1 = NORMSRC ? vbb[e]*gw1 + gb1 : vbb[e];
                    int tok = stg*16 + qd*4 + e;
                    uint32_t H, L;
                    pack2(v0, v1, H, L);
                    *(uint32_t*)&BsH[tok*ALD + 2*sdp] = H;
                    *(uint32_t*)&BsL[tok*ALD + 2*sdp] = L;
                }
            }
        }
        asm volatile("cp.async.wait_group 0;" ::: "memory");
        __syncthreads();

        #pragma unroll
        for (int k4 = 0; k4 < 4; k4++) {
            uint32_t aH[2][4], aL[2][4];
            #pragma unroll
            for (int mf = 0; mf < 2; mf++) {
                ldsm4(aH[mf][0], aH[mf][1], aH[mf][2], aH[mf][3],
                      uAH + a_off + mf*16*(ALD*2) + k4*32);
                ldsm4(aL[mf][0], aL[mf][1], aL[mf][2], aL[mf][3],
                      uAL + a_off + mf*16*(ALD*2) + k4*32);
            }
            #pragma unroll
            for (int p = 0; p < 4; p++) {
                uint32_t h0, h1, h2, h3, x0, x1, x2, x3;
                ldsm4(h0, h1, h2, h3, uBH + b_off + p*16*(ALD*2) + k4*32);
                ldsm4(x0, x1, x2, x3, uBL + b_off + p*16*(ALD*2) + k4*32);
                #pragma unroll
                for (int mf = 0; mf < 2; mf++) {
                    MMA_B16(acc[mf][2*p  ], aH[mf], h0, h1);
                    MMA_B16(acc[mf][2*p  ], aH[mf], x0, x1);
                    MMA_B16(acc[mf][2*p  ], aL[mf], h0, h1);
                    MMA_B16(acc[mf][2*p+1], aH[mf], h2, h3);
                    MMA_B16(acc[mf][2*p+1], aH[mf], x2, x3);
                    MMA_B16(acc[mf][2*p+1], aL[mf], h2, h3);
                }
            }
        }
        __syncthreads();
    }

    float gm = (EPI==1 || EPI==3) ? gamma[0] : 0.f;
    float s1 = 0.f, sq = 0.f;
    #pragma unroll
    for (int mf = 0; mf < 2; mf++) {
        int row = m0 + wm*32 + mf*16 + g;
        float bi0 = (EPI!=0) ? bias[row]     : 0.f;
        float bi8 = (EPI!=0) ? bias[row + 8] : 0.f;
        #pragma unroll
        for (int nf = 0; nf < 8; nf++) {
            int col = t0 + wn*64 + nf*8 + tq*2;
            float v00 = acc[mf][nf][0] + bi0;
            float v01 = acc[mf][nf][1] + bi0;
            float v10 = acc[mf][nf][2] + bi8;
            float v11 = acc[mf][nf][3] + bi8;
            size_t i0 = ((size_t)b*MT + row    )*NSP + col;
            size_t i8 = ((size_t)b*MT + row + 8)*NSP + col;
            if (EPI == 2) {
                v00 = v00 / (1.f + __expf(-v00));
                v01 = v01 / (1.f + __expf(-v01));
                v10 = v10 / (1.f + __expf(-v10));
                v11 = v11 / (1.f + __expf(-v11));
            } else if (EPI == 1 || EPI == 3) {
                float2 r0 = *(const float2*)(resid + i0);
                float2 r8 = *(const float2*)(resid + i8);
                v00 = r0.x + gm*v00;  v01 = r0.y + gm*v01;
                v10 = r8.x + gm*v10;  v11 = r8.y + gm*v11;
                if (EPI == 1) {
                    s1 += v00+v01+v10+v11;
                    sq += v00*v00 + v01*v01 + v10*v10 + v11*v11;
                }
            }
            *(float2*)(out + i0) = make_float2(v00, v01);
            *(float2*)(out + i8) = make_float2(v10, v11);
        }
    }
    if (EPI == 1) {
        block_reduce2(s1, sq);
        if (tid == 0) { atomicAdd(&g_sums2[b*2], s1); atomicAdd(&g_sums2[b*2+1], sq); }
    }
}

// ---------- HMMA flash attention (unchanged from passing R9) ----------
__global__ void __launch_bounds__(256) attn_mma(
    const float* __restrict__ qkv, float* __restrict__ outp)
{
    extern __shared__ __nv_bfloat16 smb[];
    __nv_bfloat16* QH = smb;
    __nv_bfloat16* QL = QH + 128*ALD;
    __nv_bfloat16* KH = QL + 128*ALD;
    __nv_bfloat16* KL = KH + 64*ALD;
    __nv_bfloat16* VH = KL + 64*ALD;
    __nv_bfloat16* VL = VH + 64*ALD;

    int it = blockIdx.x, h = blockIdx.y, b = blockIdx.z;
    int tid = threadIdx.x, lane = tid & 31, w = tid >> 5;
    int g = lane >> 2, tq = lane & 3;
    int q0 = w * 16;

    const float* qb = qkv + ((size_t)b*3*CCH +          h*DKD) * NSP + it*128;
    const float* kb = qkv + ((size_t)b*3*CCH +   CCH +  h*DKD) * NSP;
    const float* vb = qkv + ((size_t)b*3*CCH + 2*CCH +  h*DKD) * NSP;

    const int lrow = lane & 7, lt = lane >> 3;
    const uint32_t a_off = (uint32_t)((q0 + ((lt & 1) << 3) + lrow) * (ALD*2) + (lt >> 1) * 16);
    const uint32_t b_off = (uint32_t)((((lt >> 1) << 3) + lrow) * (ALD*2) + (lt & 1) * 16);
    const uint32_t uQH = s2u(QH), uQL = s2u(QL);
    const uint32_t uKH = s2u(KH), uKL = s2u(KL);
    const uint32_t uVH = s2u(VH), uVL = s2u(VL);

    {
        int dp = tid & 31, qg = tid >> 5;
        const float* p0 = qb + (size_t)(2*dp) * NSP + qg*16;
        const float* p1 = p0 + NSP;
        #pragma unroll
        for (int qd = 0; qd < 4; qd++) {
            float4 fa = *(const float4*)(p0 + qd*4);
            float4 fb = *(const float4*)(p1 + qd*4);
            float va[4] = {fa.x, fa.y, fa.z, fa.w};
            float vbb[4] = {fb.x, fb.y, fb.z, fb.w};
            #pragma unroll
            for (int e = 0; e < 4; e++) {
                int qq = qg*16 + qd*4 + e;
                uint32_t H, L;
                pack2(va[e]*0.125f, vbb[e]*0.125f, H, L);
                *(uint32_t*)&QH[qq*ALD + 2*dp] = H;
                *(uint32_t*)&QL[qq*ALD + 2*dp] = L;
            }
        }
    }

    float m0 = -1e30f, m1 = -1e30f, l0 = 0.f, l1 = 0.f;
    float oacc[8][4] = {};

    for (int kt = 0; kt < 16; kt++) {
        __syncthreads();
        {
            int dp = tid & 31, kg = tid >> 5;
            const float* p0 = kb + (size_t)(2*dp) * NSP + kt*64 + kg*8;
            const float* p1 = p0 + NSP;
            #pragma unroll
            for (int qd = 0; qd < 2; qd++) {
                float4 fa = *(const float4*)(p0 + qd*4);
                float4 fb = *(const float4*)(p1 + qd*4);
                float va[4] = {fa.x, fa.y, fa.z, fa.w};
                float vbb[4] = {fb.x, fb.y, fb.z, fb.w};
                #pragma unroll
                for (int e = 0; e < 4; e++) {
                    int key = kg*8 + qd*4 + e;
                    uint32_t H, L;
                    pack2(va[e], vbb[e], H, L);
                    *(uint32_t*)&KH[key*ALD + 2*dp] = H;
                    *(uint32_t*)&KL[key*ALD + 2*dp] = L;
                }
            }
        }
        {
            int d = tid & 63, j16 = (tid >> 6) * 16;
            const float* p = vb + (size_t)d * NSP + kt*64 + j16;
            #pragma unroll
            for (int qd = 0; qd < 2; qd++) {
                float4 fa = *(const float4*)(p + qd*8);
                float4 fb = *(const float4*)(p + qd*8 + 4);
                float f[8] = {fa.x, fa.y, fa.z, fa.w, fb.x, fb.y, fb.z, fb.w};
                uint32_t H[4], L[4];
                #pragma unroll
                for (int e = 0; e < 4; e++) pack2(f[2*e], f[2*e+1], H[e], L[e]);
                *(uint4*)&VH[d*ALD + j16 + qd*8] = make_uint4(H[0], H[1], H[2], H[3]);
                *(uint4*)&VL[d*ALD + j16 + qd*8] = make_uint4(L[0], L[1], L[2], L[3]);
            }
        }
        __syncthreads();

        float sacc[8][4] = {};
        #pragma unroll
        for (int kc = 0; kc < 4; kc++) {
            uint32_t aH[4], aL[4];
            ldsm4(aH[0], aH[1], aH[2], aH[3], uQH + a_off + kc*32);
            ldsm4(aL[0], aL[1], aL[2], aL[3], uQL + a_off + kc*32);
            #pragma unroll
            for (int p = 0; p < 4; p++) {
                uint32_t h0, h1, h2, h3, x0, x1, x2, x3;
                ldsm4(h0, h1, h2, h3, uKH + b_off + p*16*(ALD*2) + kc*32);
                ldsm4(x0, x1, x2, x3, uKL + b_off + p*16*(ALD*2) + kc*32);
                MMA_B16(sacc[2*p  ], aH, h0, h1);
                MMA_B16(sacc[2*p  ], aH, x0, x1);
                MMA_B16(sacc[2*p  ], aL, h0, h1);
                MMA_B16(sacc[2*p+1], aH, h2, h3);
                MMA_B16(sacc[2*p+1], aH, x2, x3);
                MMA_B16(sacc[2*p+1], aL, h2, h3);
            }
        }

        float rm0 = -1e30f, rm1 = -1e30f;
        #pragma unroll
        for (int nf = 0; nf < 8; nf++) {
            rm0 = fmaxf(rm0, fmaxf(sacc[nf][0], sacc[nf][1]));
            rm1 = fmaxf(rm1, fmaxf(sacc[nf][2], sacc[nf][3]));
        }
        rm0 = fmaxf(rm0, __shfl_xor_sync(0xffffffffu, rm0, 1));
        rm0 = fmaxf(rm0, __shfl_xor_sync(0xffffffffu, rm0, 2));
        rm1 = fmaxf(rm1, __shfl_xor_sync(0xffffffffu, rm1, 1));
        rm1 = fmaxf(rm1, __shfl_xor_sync(0xffffffffu, rm1, 2));
        float mn0 = fmaxf(m0, rm0), mn1 = fmaxf(m1, rm1);
        float al0 = __expf(m0 - mn0), al1 = __expf(m1 - mn1);
        m0 = mn0; m1 = mn1;
        float ls0 = 0.f, ls1 = 0.f;
        #pragma unroll
        for (int nf = 0; nf < 8; nf++) {
            sacc[nf][0] = __expf(sacc[nf][0] - mn0);
            sacc[nf][1] = __expf(sacc[nf][1] - mn0);
            sacc[nf][2] = __expf(sacc[nf][2] - mn1);
            sacc[nf][3] = __expf(sacc[nf][3] - mn1);
            ls0 += sacc[nf][0] + sacc[nf][1];
            ls1 += sacc[nf][2] + sacc[nf][3];
        }
        ls0 += __shfl_xor_sync(0xffffffffu, ls0, 1);
        ls0 += __shfl_xor_sync(0xffffffffu, ls0, 2);
        ls1 += __shfl_xor_sync(0xffffffffu, ls1, 1);
        ls1 += __shfl_xor_sync(0xffffffffu, ls1, 2);
        l0 = l0 * al0 + ls0;
        l1 = l1 * al1 + ls1;
        #pragma unroll
        for (int nf = 0; nf < 8; nf++) {
            oacc[nf][0] *= al0; oacc[nf][1] *= al0;
            oacc[nf][2] *= al1; oacc[nf][3] *= al1;
        }

        uint32_t pH[4][4], pL[4][4];
        #pragma unroll
        for (int c = 0; c < 4; c++) {
            pack2(sacc[2*c  ][0], sacc[2*c  ][1], pH[c][0], pL[c][0]);
            pack2(sacc[2*c  ][2], sacc[2*c  ][3], pH[c][1], pL[c][1]);
            pack2(sacc[2*c+1][0], sacc[2*c+1][1], pH[c][2], pL[c][2]);
            pack2(sacc[2*c+1][2], sacc[2*c+1][3], pH[c][3], pL[c][3]);
        }

        #pragma unroll
        for (int c = 0; c < 4; c++) {
            #pragma unroll
            for (int p = 0; p < 4; p++) {
                uint32_t h0, h1, h2, h3, x0, x1, x2, x3;
                ldsm4(h0, h1, h2, h3, uVH + b_off + p*16*(ALD*2) + c*32);
                ldsm4(x0, x1, x2, x3, uVL + b_off + p*16*(ALD*2) + c*32);
                MMA_B16(oacc[2*p  ], pH[c], h0, h1);
                MMA_B16(oacc[2*p  ], pH[c], x0, x1);
                MMA_B16(oacc[2*p  ], pL[c], h0, h1);
                MMA_B16(oacc[2*p+1], pH[c], h2, h3);
                MMA_B16(oacc[2*p+1], pH[c], x2, x3);
                MMA_B16(oacc[2*p+1], pL[c], h2, h3);
            }
        }
    }

    __syncthreads();
    float inv0 = 1.f / l0, inv1 = 1.f / l1;
    float* OS = (float*)smb;
    #pragma unroll
    for (int nf = 0; nf < 8; nf++) {
        int d = nf*8 + 2*tq;
        OS[(d  )*128 + q0 + g    ] = oacc[nf][0] * inv0;
        OS[(d+1)*128 + q0 + g    ] = oacc[nf][1] * inv0;
        OS[(d  )*128 + q0 + g + 8] = oacc[nf][2] * inv1;
        OS[(d+1)*128 + q0 + g + 8] = oacc[nf][3] * inv1;
    }
    __syncthreads();
    {
        int d = tid >> 2, q32 = (tid & 3) * 32;
        float* ob = outp + ((size_t)b*CCH + h*DKD + d)*NSP + it*128 + q32;
        #pragma unroll
        for (int j = 0; j < 8; j++)
            *(float4*)(ob + j*4) = *(const float4*)&OS[d*128 + q32 + j*4];
    }
}

// ---------- launch ----------
#define ATTN_SMEM ((2*128 + 4*64)*ALD*2)
#define GEMM_SMEM (4*128*ALD*2)

extern "C" void kernel_launch(void* const* d_in, const int* in_sizes, int n_in,
                              void* d_out, int out_size) {
    const float* x     = (const float*)d_in[0];
    const float* qkv_w = (const float*)d_in[1];
    const float* uh_w  = (const float*)d_in[2];
    const float* uh_b  = (const float*)d_in[3];
    const float* n1_w  = (const float*)d_in[4];
    const float* n1_b  = (const float*)d_in[5];
    const float* n2_w  = (const float*)d_in[6];
    const float* n2_b  = (const float*)d_in[7];
    const float* f1_w  = (const float*)d_in[8];
    const float* f1_b  = (const float*)d_in[9];
    const float* f2_w  = (const float*)d_in[10];
    const float* f2_b  = (const float*)d_in[11];
    const float* g_at  = (const float*)d_in[12];
    const float* g_ff  = (const float*)d_in[13];
    float* out = (float*)d_out;

    float *qkv_buf, *attn_buf, *x2_buf, *h1_buf;
    __nv_bfloat16 *wH, *wL;
    cudaGetSymbolAddress((void**)&qkv_buf,  g_qkv);
    cudaGetSymbolAddress((void**)&attn_buf, g_attn);
    cudaGetSymbolAddress((void**)&x2_buf,   g_x2);
    cudaGetSymbolAddress((void**)&h1_buf,   g_h1);
    cudaGetSymbolAddress((void**)&wH, g_wH);
    cudaGetSymbolAddress((void**)&wL, g_wL);

    cudaFuncSetAttribute(attn_mma, cudaFuncAttributeMaxDynamicSharedMemorySize, ATTN_SMEM);
    cudaFuncSetAttribute(gemm_mma<256,1,0>,  cudaFuncAttributeMaxDynamicSharedMemorySize, GEMM_SMEM);
    cudaFuncSetAttribute(gemm_mma<256,0,1>,  cudaFuncAttributeMaxDynamicSharedMemorySize, GEMM_SMEM);
    cudaFuncSetAttribute(gemm_mma<256,2,2>,  cudaFuncAttributeMaxDynamicSharedMemorySize, GEMM_SMEM);
    cudaFuncSetAttribute(gemm_mma<1024,0,3>, cudaFuncAttributeMaxDynamicSharedMemorySize, GEMM_SMEM);

    zero_stats_kernel<<<1, 32>>>();
    gn_stats_kernel<<<dim3(32, BSZ), 256>>>(x);

    // one-shot weight split
    convert_w_kernel<<<(196608/2 + 255)/256, 256>>>(qkv_w, wH + W_QKV, wL + W_QKV, 196608/2);
    convert_w_kernel<<<( 65536/2 + 255)/256, 256>>>(uh_w,  wH + W_UH,  wL + W_UH,   65536/2);
    convert_w_kernel<<<(262144/2 + 255)/256, 256>>>(f1_w,  wH + W_F1,  wL + W_F1,  262144/2);
    convert_w_kernel<<<(262144/2 + 255)/256, 256>>>(f2_w,  wH + W_F2,  wL + W_F2,  262144/2);

    // qkv = qkv_w @ GN1(x)
    gemm_mma<256,1,0><<<dim3(8,6,BSZ), 256, GEMM_SMEM>>>(
        x, wH + W_QKV, wL + W_QKV, n1_w, n1_b, nullptr, nullptr, nullptr, qkv_buf);

    attn_mma<<<dim3(8, NHH, BSZ), 256, ATTN_SMEM>>>(qkv_buf, attn_buf);

    // x2 = x + g_at*(uh_w@attn + uh_b), + GN2 stats
    gemm_mma<256,0,1><<<dim3(8,2,BSZ), 256, GEMM_SMEM>>>(
        attn_buf, wH + W_UH, wL + W_UH, nullptr, nullptr, uh_b, x, g_at, x2_buf);

    // h1 = silu(f1_w @ GN2(x2) + f1_b)
    gemm_mma<256,2,2><<<dim3(8,8,BSZ), 256, GEMM_SMEM>>>(
        x2_buf, wH + W_F1, wL + W_F1, n2_w, n2_b, f1_b, nullptr, nullptr, h1_buf);

    // out = x2 + g_ff*(f2_w@h1 + f2_b)
    gemm_mma<1024,0,3><<<dim3(8,2,BSZ), 256, GEMM_SMEM>>>(
        h1_buf, wH + W_F2, wL + W_F2, nullptr, nullptr, f2_b, x2_buf, g_ff, out);
}